// round 9
// baseline (speedup 1.0000x reference)
#include <cuda_runtime.h>
#include <cstdint>

#define NE   8
#define NH   1024
#define NM   2048
#define NTOK 2048
#define SLOT_CAP     6144
#define SHARED_HBASE 6144
#define HROWS        8192
#define MAX_TILES    96

// A smem (64 rows): [16 kgroups][4 mblocks][8 pairs][4 slots] + 8 pad -> stride 136
#define AKG  136
#define A_BUF 2176          // 16 * 136 floats
#define BRS  264            // B row stride (128 n * 2 interleaved + 8 pad)
#define B1_BUF 8448         // 32 * 264 (gate/up interleaved)
#define B2_BUF 4224         // 16 * 264 (k, k+4 interleaved)

// ---------------- device scratch ----------------
__device__ int   g_rows[SLOT_CAP];
__device__ int   g_tile_e[MAX_TILES];
__device__ int   g_tile_base[MAX_TILES];
__device__ int   g_num_tiles;
__device__ int   g_topk_idx[NTOK * 2];
__device__ float g_topk_prob[NTOK * 2];
__device__ int   g_tok2slot[NTOK * 2];
__device__ float g_hbuf[(size_t)HROWS * NM];
__device__ float g_eout[(size_t)SLOT_CAP * NH];

// ---------------- helpers ----------------
__device__ __forceinline__ float to_tf32(float v) {
    uint32_t r;
    asm("cvt.rna.tf32.f32 %0, %1;" : "=r"(r) : "f"(v));
    return __uint_as_float(r);
}
__device__ __forceinline__ float silu_f(float v) { return v / (1.0f + __expf(-v)); }

__device__ __forceinline__ void mma8(float* d, const uint32_t* a, uint32_t b0, uint32_t b1) {
    asm volatile(
        "mma.sync.aligned.m16n8k8.row.col.f32.tf32.tf32.f32 "
        "{%0,%1,%2,%3},{%4,%5,%6,%7},{%8,%9},{%0,%1,%2,%3};"
        : "+f"(d[0]), "+f"(d[1]), "+f"(d[2]), "+f"(d[3])
        : "r"(a[0]), "r"(a[1]), "r"(a[2]), "r"(a[3]), "r"(b0), "r"(b1));
}

// A tile store: element (k 0..31, r 0..63) ->
//   kg = (k>>3)*4 + (k&3); addr = kg*AKG + (r>>4)*32 + (r&7)*4 + slot
//   slot = (((k>>2)&1)*2 + ((r>>3)&1)) ^ (((r>>4)&1)*2)
__device__ __forceinline__ void sts_a8(float* as, int row_a, int q0,
                                       float4 v0, float4 v1) {
    int blk = row_a >> 4;
    int rbase = blk * 32 + (row_a & 7) * 4 + ((row_a >> 3) & 1);
    int h = ((q0 & 1) ^ (blk & 1)) << 1;
    int kg0 = ((q0 >> 1) << 2);
    float* p0 = as + kg0 * AKG + rbase + h;
    p0[0 * AKG] = to_tf32(v0.x);
    p0[1 * AKG] = to_tf32(v0.y);
    p0[2 * AKG] = to_tf32(v0.z);
    p0[3 * AKG] = to_tf32(v0.w);
    float* p1 = p0 + 8 * AKG;
    p1[0 * AKG] = to_tf32(v1.x);
    p1[1 * AKG] = to_tf32(v1.y);
    p1[2 * AKG] = to_tf32(v1.z);
    p1[3 * AKG] = to_tf32(v1.w);
}

// Load both 16-row A fragments (blocks ablk0, ablk0+1; ablk0 even)
__device__ __forceinline__ void lds_a2(const float* as, int kgj, int ablk0, int g,
                                       uint32_t a[2][4]) {
    float4 f0 = *(const float4*)&as[kgj + ablk0 * 32 + g * 4];
    a[0][0] = __float_as_uint(f0.x); a[0][1] = __float_as_uint(f0.y);
    a[0][2] = __float_as_uint(f0.z); a[0][3] = __float_as_uint(f0.w);
    float4 f1 = *(const float4*)&as[kgj + (ablk0 + 1) * 32 + g * 4];
    a[1][0] = __float_as_uint(f1.z); a[1][1] = __float_as_uint(f1.w);
    a[1][2] = __float_as_uint(f1.x); a[1][3] = __float_as_uint(f1.y);
}

// ---------------- routing ----------------
__global__ void moe_route(const float* __restrict__ x,
                          const float* __restrict__ gw,
                          const float* __restrict__ beta) {
    int b = blockIdx.x;
    const float* xr = x + (size_t)b * NH;
    float acc[NE];
#pragma unroll
    for (int e = 0; e < NE; e++) acc[e] = 0.f;
    for (int h = threadIdx.x; h < NH; h += 256) {
        float xv = xr[h];
#pragma unroll
        for (int e = 0; e < NE; e++) acc[e] += xv * gw[e * NH + h];
    }
#pragma unroll
    for (int off = 16; off > 0; off >>= 1)
#pragma unroll
        for (int e = 0; e < NE; e++)
            acc[e] += __shfl_down_sync(0xFFFFFFFFu, acc[e], off);
    __shared__ float part[8][NE];
    int lane = threadIdx.x & 31, warp = threadIdx.x >> 5;
    if (lane == 0)
#pragma unroll
        for (int e = 0; e < NE; e++) part[warp][e] = acc[e];
    __syncthreads();
    if (threadIdx.x == 0) {
        float lg[NE];
#pragma unroll
        for (int e = 0; e < NE; e++) {
            float s = 0.f;
#pragma unroll
            for (int w = 0; w < 8; w++) s += part[w][e];
            lg[e] = s;
        }
        int i1 = 0; float b1 = -1e30f;
#pragma unroll
        for (int e = 0; e < NE; e++) {
            float v = lg[e] + beta[e];
            if (v > b1) { b1 = v; i1 = e; }
        }
        int i2 = -1; float b2 = -1e30f;
#pragma unroll
        for (int e = 0; e < NE; e++) {
            if (e == i1) continue;
            float v = lg[e] + beta[e];
            if (v > b2) { b2 = v; i2 = e; }
        }
        g_topk_idx[2 * b + 0] = i1;
        g_topk_prob[2 * b + 0] = 1.f / (1.f + __expf(-lg[i1]));
        g_topk_idx[2 * b + 1] = i2;
        g_topk_prob[2 * b + 1] = 1.f / (1.f + __expf(-lg[i2]));
    }
}

__global__ void moe_build() {
    __shared__ int cnt[NE], fill[NE], seg[NE];
    int tid = threadIdx.x;
    for (int i = tid; i < SLOT_CAP; i += blockDim.x) g_rows[i] = -1;
    if (tid < NE) { cnt[tid] = 0; fill[tid] = 0; }
    __syncthreads();
    for (int i = tid; i < NTOK * 2; i += blockDim.x)
        atomicAdd(&cnt[g_topk_idx[i]], 1);
    __syncthreads();
    if (tid == 0) {
        int off = 0, nt = 0;
        for (int e = 0; e < NE; e++) {
            seg[e] = off;
            int tiles = (cnt[e] + 63) >> 6;
            for (int t = 0; t < tiles; t++) {
                g_tile_e[nt] = e;
                g_tile_base[nt] = off + (t << 6);
                nt++;
            }
            off += tiles << 6;
        }
        g_num_tiles = nt;
    }
    __syncthreads();
    for (int i = tid; i < NTOK * 2; i += blockDim.x) {
        int e = g_topk_idx[i];
        int p = seg[e] + atomicAdd(&fill[e], 1);
        g_rows[p] = i >> 1;
        g_tok2slot[i] = p;
    }
}

// ---------------- GEMM1: h = silu(x@Wg)*(x@Wu), CTA 64m x 128n, 256 thr ----------------
#define SMEM1_BYTES ((2 * A_BUF + 2 * B1_BUF) * 4)

template <bool SHARED>
__global__ void __launch_bounds__(256, 2)
moe_gemm1_mma(const float* __restrict__ x,
              const float* __restrict__ Wg,
              const float* __restrict__ Wu) {
    extern __shared__ float sm[];
    int by = blockIdx.y, e, base;
    if (SHARED) { e = 0; base = by * 64; }
    else {
        if (by >= g_num_tiles) return;
        e = g_tile_e[by];
        base = g_tile_base[by];
    }
    const int m0 = blockIdx.x * 128;
    const float* wg = Wg + (size_t)e * NH * NM;
    const float* wu = Wu + (size_t)e * NH * NM;

    float* As = sm;                   // [2][A_BUF]
    float* Bs = sm + 2 * A_BUF;       // [2][B1_BUF] gate/up interleaved

    const int tid = threadIdx.x;
    const int lane = tid & 31, wid = tid >> 5;   // 8 warps
    const int j = lane & 3, g = lane >> 2;
    const int wm = (wid & 1) * 32, wn = (wid >> 1) * 32;
    const int ablk0 = (wid & 1) * 2;

    const int row_a = tid & 63, q0 = tid >> 6;   // q0 0..3
    int tok = SHARED ? (base + row_a) : g_rows[base + row_a];
    const bool okA = (tok >= 0);
    const float* ax = x + (size_t)(okA ? tok : 0) * NH;
    const int bn4 = (tid & 31) * 4, bk = tid >> 5;   // bk 0..7 (+8, +16, +24)

    float dg[2][4][4], du[2][4][4];
#pragma unroll
    for (int a1 = 0; a1 < 2; a1++)
#pragma unroll
        for (int b1 = 0; b1 < 4; b1++)
#pragma unroll
            for (int c1 = 0; c1 < 4; c1++) { dg[a1][b1][c1] = 0.f; du[a1][b1][c1] = 0.f; }

    const float4 z4 = make_float4(0.f, 0.f, 0.f, 0.f);
    float4 va0, va1, vg0, vu0, vg1, vu1, vg2, vu2, vg3, vu3;
    va0 = okA ? *(const float4*)(ax + 4 * q0) : z4;
    va1 = okA ? *(const float4*)(ax + 4 * q0 + 16) : z4;
    vg0 = *(const float4*)(wg + (size_t)bk * NM + m0 + bn4);
    vu0 = *(const float4*)(wu + (size_t)bk * NM + m0 + bn4);
    vg1 = *(const float4*)(wg + (size_t)(bk + 8) * NM + m0 + bn4);
    vu1 = *(const float4*)(wu + (size_t)(bk + 8) * NM + m0 + bn4);
    vg2 = *(const float4*)(wg + (size_t)(bk + 16) * NM + m0 + bn4);
    vu2 = *(const float4*)(wu + (size_t)(bk + 16) * NM + m0 + bn4);
    vg3 = *(const float4*)(wg + (size_t)(bk + 24) * NM + m0 + bn4);
    vu3 = *(const float4*)(wu + (size_t)(bk + 24) * NM + m0 + bn4);

    const int KC = NH / 32;
    int buf = 0;
    {
        sts_a8(As, row_a, q0, va0, va1);
        float* b = Bs + bk * BRS + bn4 * 2;
        *(float4*)(b)     = make_float4(to_tf32(vg0.x), to_tf32(vu0.x), to_tf32(vg0.y), to_tf32(vu0.y));
        *(float4*)(b + 4) = make_float4(to_tf32(vg0.z), to_tf32(vu0.z), to_tf32(vg0.w), to_tf32(vu0.w));
        float* b1p = b + 8 * BRS;
        *(float4*)(b1p)     = make_float4(to_tf32(vg1.x), to_tf32(vu1.x), to_tf32(vg1.y), to_tf32(vu1.y));
        *(float4*)(b1p + 4) = make_float4(to_tf32(vg1.z), to_tf32(vu1.z), to_tf32(vg1.w), to_tf32(vu1.w));
        float* b2p = b + 16 * BRS;
        *(float4*)(b2p)     = make_float4(to_tf32(vg2.x), to_tf32(vu2.x), to_tf32(vg2.y), to_tf32(vu2.y));
        *(float4*)(b2p + 4) = make_float4(to_tf32(vg2.z), to_tf32(vu2.z), to_tf32(vg2.w), to_tf32(vu2.w));
        float* b3p = b + 24 * BRS;
        *(float4*)(b3p)     = make_float4(to_tf32(vg3.x), to_tf32(vu3.x), to_tf32(vg3.y), to_tf32(vu3.y));
        *(float4*)(b3p + 4) = make_float4(to_tf32(vg3.z), to_tf32(vu3.z), to_tf32(vg3.w), to_tf32(vu3.w));
    }
    __syncthreads();

    for (int kc = 0; kc < KC; kc++) {
        if (kc + 1 < KC) {
            int k0 = (kc + 1) * 32;
            va0 = okA ? *(const float4*)(ax + k0 + 4 * q0) : z4;
            va1 = okA ? *(const float4*)(ax + k0 + 4 * q0 + 16) : z4;
            vg0 = *(const float4*)(wg + (size_t)(k0 + bk) * NM + m0 + bn4);
            vu0 = *(const float4*)(wu + (size_t)(k0 + bk) * NM + m0 + bn4);
            vg1 = *(const float4*)(wg + (size_t)(k0 + bk + 8) * NM + m0 + bn4);
            vu1 = *(const float4*)(wu + (size_t)(k0 + bk + 8) * NM + m0 + bn4);
            vg2 = *(const float4*)(wg + (size_t)(k0 + bk + 16) * NM + m0 + bn4);
            vu2 = *(const float4*)(wu + (size_t)(k0 + bk + 16) * NM + m0 + bn4);
            vg3 = *(const float4*)(wg + (size_t)(k0 + bk + 24) * NM + m0 + bn4);
            vu3 = *(const float4*)(wu + (size_t)(k0 + bk + 24) * NM + m0 + bn4);
        }
        const float* as = As + buf * A_BUF;
        const float* bs = Bs + buf * B1_BUF;
#pragma unroll
        for (int s = 0; s < 4; s++) {
            const int kgj = (4 * s + j) * AKG;
            const int krj = (8 * s + j) * BRS;
            uint32_t a[2][4];
            lds_a2(as, kgj, ablk0, g, a);
#pragma unroll
            for (int ni = 0; ni < 4; ni++) {
                int c2 = (wn + 8 * ni + g) * 2;
                float2 p0 = *(const float2*)&bs[krj + c2];
                float2 p1 = *(const float2*)&bs[krj + 4 * BRS + c2];
                uint32_t g0 = __float_as_uint(p0.x), u0 = __float_as_uint(p0.y);
                uint32_t g1 = __float_as_uint(p1.x), u1 = __float_as_uint(p1.y);
#pragma unroll
                for (int mi = 0; mi < 2; mi++) {
                    mma8(dg[mi][ni], a[mi], g0, g1);
                    mma8(du[mi][ni], a[mi], u0, u1);
                }
            }
        }
        if (kc + 1 < KC) {
            buf ^= 1;
            float* asw = As + buf * A_BUF;
            float* bsw = Bs + buf * B1_BUF;
            sts_a8(asw, row_a, q0, va0, va1);
            float* b = bsw + bk * BRS + bn4 * 2;
            *(float4*)(b)     = make_float4(to_tf32(vg0.x), to_tf32(vu0.x), to_tf32(vg0.y), to_tf32(vu0.y));
            *(float4*)(b + 4) = make_float4(to_tf32(vg0.z), to_tf32(vu0.z), to_tf32(vg0.w), to_tf32(vu0.w));
            float* b1p = b + 8 * BRS;
            *(float4*)(b1p)     = make_float4(to_tf32(vg1.x), to_tf32(vu1.x), to_tf32(vg1.y), to_tf32(vu1.y));
            *(float4*)(b1p + 4) = make_float4(to_tf32(vg1.z), to_tf32(vu1.z), to_tf32(vg1.w), to_tf32(vu1.w));
            float* b2p = b + 16 * BRS;
            *(float4*)(b2p)     = make_float4(to_tf32(vg2.x), to_tf32(vu2.x), to_tf32(vg2.y), to_tf32(vu2.y));
            *(float4*)(b2p + 4) = make_float4(to_tf32(vg2.z), to_tf32(vu2.z), to_tf32(vg2.w), to_tf32(vu2.w));
            float* b3p = b + 24 * BRS;
            *(float4*)(b3p)     = make_float4(to_tf32(vg3.x), to_tf32(vu3.x), to_tf32(vg3.y), to_tf32(vu3.y));
            *(float4*)(b3p + 4) = make_float4(to_tf32(vg3.z), to_tf32(vu3.z), to_tf32(vg3.w), to_tf32(vu3.w));
            __syncthreads();
        }
    }

    const int hb = (SHARED ? SHARED_HBASE : 0) + base;
#pragma unroll
    for (int mi = 0; mi < 2; mi++)
#pragma unroll
        for (int ni = 0; ni < 4; ni++) {
            int r = hb + wm + 16 * mi + g;
            int col = m0 + wn + 8 * ni + 2 * j;
            float2 h0, h1;
            h0.x = silu_f(dg[mi][ni][0]) * du[mi][ni][0];
            h0.y = silu_f(dg[mi][ni][1]) * du[mi][ni][1];
            h1.x = silu_f(dg[mi][ni][2]) * du[mi][ni][2];
            h1.y = silu_f(dg[mi][ni][3]) * du[mi][ni][3];
            *(float2*)&g_hbuf[(size_t)r * NM + col] = h0;
            *(float2*)&g_hbuf[(size_t)(r + 8) * NM + col] = h1;
        }
}

// ---------------- GEMM2: out/eout = h @ Wd, CTA 64m x 128n, 256 thr ----------------
#define SMEM2_BYTES ((2 * A_BUF + 2 * B2_BUF) * 4)

template <bool SHARED>
__global__ void __launch_bounds__(256, 2)
moe_gemm2_mma(const float* __restrict__ Wd, float* __restrict__ out) {
    extern __shared__ float sm[];
    int by = blockIdx.y, e, base;
    if (SHARED) { e = 0; base = by * 64; }
    else {
        if (by >= g_num_tiles) return;
        e = g_tile_e[by];
        base = g_tile_base[by];
    }
    const int n0 = blockIdx.x * 128;
    const float* wd = Wd + (size_t)e * NM * NH;
    const int hb = (SHARED ? SHARED_HBASE : 0) + base;

    float* As = sm;                   // [2][A_BUF]
    float* Bs = sm + 2 * A_BUF;       // [2][B2_BUF] (k, k+4) interleaved

    const int tid = threadIdx.x;
    const int lane = tid & 31, wid = tid >> 5;
    const int j = lane & 3, g = lane >> 2;
    const int wm = (wid & 1) * 32, wn = (wid >> 1) * 32;
    const int ablk0 = (wid & 1) * 2;

    const int row_a = tid & 63, q0 = tid >> 6;
    const float* ax = g_hbuf + (size_t)(hb + row_a) * NM;
    const int bn4 = (tid & 31) * 4;
    const int kb = tid >> 5;                          // 0..7; also kb+8
    const int klo = ((kb >> 2) << 3) + (kb & 3);      // pair base k (rows klo, klo+4)
    // second set: pair-row kb+8 -> k rows klo+16, klo+20

    float d[2][4][4];
#pragma unroll
    for (int a1 = 0; a1 < 2; a1++)
#pragma unroll
        for (int b1 = 0; b1 < 4; b1++)
#pragma unroll
            for (int c1 = 0; c1 < 4; c1++) d[a1][b1][c1] = 0.f;

    float4 va0, va1, vb0, vb1, vb2, vb3;
    va0 = *(const float4*)(ax + 4 * q0);
    va1 = *(const float4*)(ax + 4 * q0 + 16);
    vb0 = *(const float4*)(wd + (size_t)klo * NH + n0 + bn4);
    vb1 = *(const float4*)(wd + (size_t)(klo + 4) * NH + n0 + bn4);
    vb2 = *(const float4*)(wd + (size_t)(klo + 16) * NH + n0 + bn4);
    vb3 = *(const float4*)(wd + (size_t)(klo + 20) * NH + n0 + bn4);

    const int KC = NM / 32;
    int buf = 0;
    {
        sts_a8(As, row_a, q0, va0, va1);
        float* b = Bs + kb * BRS + bn4 * 2;
        *(float4*)(b)     = make_float4(to_tf32(vb0.x), to_tf32(vb1.x), to_tf32(vb0.y), to_tf32(vb1.y));
        *(float4*)(b + 4) = make_float4(to_tf32(vb0.z), to_tf32(vb1.z), to_tf32(vb0.w), to_tf32(vb1.w));
        float* b2p = b + 8 * BRS;
        *(float4*)(b2p)     = make_float4(to_tf32(vb2.x), to_tf32(vb3.x), to_tf32(vb2.y), to_tf32(vb3.y));
        *(float4*)(b2p + 4) = make_float4(to_tf32(vb2.z), to_tf32(vb3.z), to_tf32(vb2.w), to_tf32(vb3.w));
    }
    __syncthreads();

    for (int kc = 0; kc < KC; kc++) {
        if (kc + 1 < KC) {
            int k0 = (kc + 1) * 32;
            va0 = *(const float4*)(ax + k0 + 4 * q0);
            va1 = *(const float4*)(ax + k0 + 4 * q0 + 16);
            vb0 = *(const float4*)(wd + (size_t)(k0 + klo) * NH + n0 + bn4);
            vb1 = *(const float4*)(wd + (size_t)(k0 + klo + 4) * NH + n0 + bn4);
            vb2 = *(const float4*)(wd + (size_t)(k0 + klo + 16) * NH + n0 + bn4);
            vb3 = *(const float4*)(wd + (size_t)(k0 + klo + 20) * NH + n0 + bn4);
        }
        const float* as = As + buf * A_BUF;
        const float* bs = Bs + buf * B2_BUF;
#pragma unroll
        for (int s = 0; s < 4; s++) {
            const int kgj = (4 * s + j) * AKG;
            const int krj = (4 * s + j) * BRS;
            uint32_t a[2][4];
            lds_a2(as, kgj, ablk0, g, a);
#pragma unroll
            for (int ni = 0; ni < 4; ni++) {
                int c2 = (wn + 8 * ni + g) * 2;
                float2 p = *(const float2*)&bs[krj + c2];
                uint32_t b0 = __float_as_uint(p.x), b1 = __float_as_uint(p.y);
#pragma unroll
                for (int mi = 0; mi < 2; mi++)
                    mma8(d[mi][ni], a[mi], b0, b1);
            }
        }
        if (kc + 1 < KC) {
            buf ^= 1;
            float* asw = As + buf * A_BUF;
            float* bsw = Bs + buf * B2_BUF;
            sts_a8(asw, row_a, q0, va0, va1);
            float* b = bsw + kb * BRS + bn4 * 2;
            *(float4*)(b)     = make_float4(to_tf32(vb0.x), to_tf32(vb1.x), to_tf32(vb0.y), to_tf32(vb1.y));
            *(float4*)(b + 4) = make_float4(to_tf32(vb0.z), to_tf32(vb1.z), to_tf32(vb0.w), to_tf32(vb1.w));
            float* b2p = b + 8 * BRS;
            *(float4*)(b2p)     = make_float4(to_tf32(vb2.x), to_tf32(vb3.x), to_tf32(vb2.y), to_tf32(vb3.y));
            *(float4*)(b2p + 4) = make_float4(to_tf32(vb2.z), to_tf32(vb3.z), to_tf32(vb2.w), to_tf32(vb3.w));
            __syncthreads();
        }
    }

#pragma unroll
    for (int mi = 0; mi < 2; mi++)
#pragma unroll
        for (int ni = 0; ni < 4; ni++) {
            int r = base + wm + 16 * mi + g;
            int col = n0 + wn + 8 * ni + 2 * j;
            float* dst0 = SHARED ? (out + (size_t)r * NH + col)
                                 : (g_eout + (size_t)r * NH + col);
            float* dst1 = SHARED ? (out + (size_t)(r + 8) * NH + col)
                                 : (g_eout + (size_t)(r + 8) * NH + col);
            *(float2*)dst0 = make_float2(d[mi][ni][0], d[mi][ni][1]);
            *(float2*)dst1 = make_float2(d[mi][ni][2], d[mi][ni][3]);
        }
}

// ---------------- combine ----------------
__global__ void moe_combine(float* __restrict__ out) {
    int t = blockIdx.x;
    int h = threadIdx.x * 4;
    int s0 = g_tok2slot[2 * t + 0], s1 = g_tok2slot[2 * t + 1];
    float p0 = g_topk_prob[2 * t + 0], p1 = g_topk_prob[2 * t + 1];
    float4 o = *(float4*)(out + (size_t)t * NH + h);
    float4 a = *(const float4*)(g_eout + (size_t)s0 * NH + h);
    float4 b = *(const float4*)(g_eout + (size_t)s1 * NH + h);
    o.x += p0 * a.x + p1 * b.x;
    o.y += p0 * a.y + p1 * b.y;
    o.z += p0 * a.z + p1 * b.z;
    o.w += p0 * a.w + p1 * b.w;
    *(float4*)(out + (size_t)t * NH + h) = o;
}

// ---------------- launch ----------------
extern "C" void kernel_launch(void* const* d_in, const int* in_sizes, int n_in,
                              void* d_out, int out_size) {
    const float* x    = (const float*)d_in[0];
    const float* gw   = (const float*)d_in[1];
    const float* beta = (const float*)d_in[2];
    const float* gpw  = (const float*)d_in[3];
    const float* upw  = (const float*)d_in[4];
    const float* dpw  = (const float*)d_in[5];
    const float* sgw  = (const float*)d_in[6];
    const float* suw  = (const float*)d_in[7];
    const float* sdw  = (const float*)d_in[8];
    float* out = (float*)d_out;

    cudaFuncSetAttribute(moe_gemm1_mma<false>, cudaFuncAttributeMaxDynamicSharedMemorySize, SMEM1_BYTES);
    cudaFuncSetAttribute(moe_gemm1_mma<true>,  cudaFuncAttributeMaxDynamicSharedMemorySize, SMEM1_BYTES);
    cudaFuncSetAttribute(moe_gemm2_mma<false>, cudaFuncAttributeMaxDynamicSharedMemorySize, SMEM2_BYTES);
    cudaFuncSetAttribute(moe_gemm2_mma<true>,  cudaFuncAttributeMaxDynamicSharedMemorySize, SMEM2_BYTES);

    moe_route<<<NTOK, 256>>>(x, gw, beta);
    moe_build<<<1, 512>>>();

    // routed tiles: padded to 64 rows; max tiles = 4096/64 + 8 = 72
    moe_gemm1_mma<false><<<dim3(NM / 128, 72), 256, SMEM1_BYTES>>>(x, gpw, upw);
    moe_gemm1_mma<true> <<<dim3(NM / 128, NTOK / 64), 256, SMEM1_BYTES>>>(x, sgw, suw);

    moe_gemm2_mma<true> <<<dim3(NH / 128, NTOK / 64), 256, SMEM2_BYTES>>>(sdw, out);
    moe_gemm2_mma<false><<<dim3(NH / 128, 72), 256, SMEM2_BYTES>>>(dpw, out);

    moe_combine<<<NTOK, 256>>>(out);
}

// round 11
// speedup vs baseline: 1.7309x; 1.7309x over previous
#include <cuda_runtime.h>
#include <cuda_fp16.h>
#include <cstdint>

#define NE   8
#define NH   1024
#define NM   2048
#define NTOK 2048
#define SLOT_CAP     6144
#define SHARED_HBASE 6144
#define HROWS        8192
#define MAX_TILES    48

// fp16 smem layouts (word = 4B = 2 fp16)
#define A_W    20      // words per A row (32 fp16 data + 8 pad) -> LDSM stride conflict-free
#define A_BUFW 2560    // 128 * 20
#define B_W    68      // words per B row (128 fp16 data + 8 pad) -> 4k mod 32 banks
#define B_BUFW 2176    // 32 * 68

// ---------------- device scratch ----------------
__device__ int   g_rows[SLOT_CAP];
__device__ int   g_tile_e[MAX_TILES];
__device__ int   g_tile_base[MAX_TILES];
__device__ int   g_num_tiles;
__device__ int   g_topk_idx[NTOK * 2];
__device__ float g_topk_prob[NTOK * 2];
__device__ int   g_tok2slot[NTOK * 2];
__device__ float g_hbuf[(size_t)HROWS * NM];
__device__ float g_eout[(size_t)SLOT_CAP * NH];

// ---------------- helpers ----------------
__device__ __forceinline__ uint32_t smem_u32(const void* p) {
    uint32_t a;
    asm("{ .reg .u64 t; cvta.to.shared.u64 t, %1; cvt.u32.u64 %0, t; }" : "=r"(a) : "l"(p));
    return a;
}
__device__ __forceinline__ uint32_t pack2(float lo, float hi) {
    __half2 h = __floats2half2_rn(lo, hi);
    return *(uint32_t*)&h;
}
__device__ __forceinline__ float silu_f(float v) { return v / (1.0f + __expf(-v)); }

__device__ __forceinline__ void ldsm4(uint32_t* r, uint32_t addr) {
    asm volatile("ldmatrix.sync.aligned.m8n8.x4.shared.b16 {%0,%1,%2,%3}, [%4];"
        : "=r"(r[0]), "=r"(r[1]), "=r"(r[2]), "=r"(r[3]) : "r"(addr));
}
__device__ __forceinline__ void ldsm4t(uint32_t* r, uint32_t addr) {
    asm volatile("ldmatrix.sync.aligned.m8n8.x4.trans.shared.b16 {%0,%1,%2,%3}, [%4];"
        : "=r"(r[0]), "=r"(r[1]), "=r"(r[2]), "=r"(r[3]) : "r"(addr));
}
__device__ __forceinline__ void mma16(float* d, const uint32_t* a, uint32_t b0, uint32_t b1) {
    asm volatile(
        "mma.sync.aligned.m16n8k16.row.col.f32.f16.f16.f32 "
        "{%0,%1,%2,%3},{%4,%5,%6,%7},{%8,%9},{%0,%1,%2,%3};"
        : "+f"(d[0]), "+f"(d[1]), "+f"(d[2]), "+f"(d[3])
        : "r"(a[0]), "r"(a[1]), "r"(a[2]), "r"(a[3]), "r"(b0), "r"(b1));
}

// ---------------- routing ----------------
__global__ void moe_route(const float* __restrict__ x,
                          const float* __restrict__ gw,
                          const float* __restrict__ beta) {
    int b = blockIdx.x;
    const float* xr = x + (size_t)b * NH;
    float acc[NE];
#pragma unroll
    for (int e = 0; e < NE; e++) acc[e] = 0.f;
    for (int h = threadIdx.x; h < NH; h += 256) {
        float xv = xr[h];
#pragma unroll
        for (int e = 0; e < NE; e++) acc[e] += xv * gw[e * NH + h];
    }
#pragma unroll
    for (int off = 16; off > 0; off >>= 1)
#pragma unroll
        for (int e = 0; e < NE; e++)
            acc[e] += __shfl_down_sync(0xFFFFFFFFu, acc[e], off);
    __shared__ float part[8][NE];
    int lane = threadIdx.x & 31, warp = threadIdx.x >> 5;
    if (lane == 0)
#pragma unroll
        for (int e = 0; e < NE; e++) part[warp][e] = acc[e];
    __syncthreads();
    if (threadIdx.x == 0) {
        float lg[NE];
#pragma unroll
        for (int e = 0; e < NE; e++) {
            float s = 0.f;
#pragma unroll
            for (int w = 0; w < 8; w++) s += part[w][e];
            lg[e] = s;
        }
        int i1 = 0; float b1 = -1e30f;
#pragma unroll
        for (int e = 0; e < NE; e++) {
            float v = lg[e] + beta[e];
            if (v > b1) { b1 = v; i1 = e; }
        }
        int i2 = -1; float b2 = -1e30f;
#pragma unroll
        for (int e = 0; e < NE; e++) {
            if (e == i1) continue;
            float v = lg[e] + beta[e];
            if (v > b2) { b2 = v; i2 = e; }
        }
        g_topk_idx[2 * b + 0] = i1;
        g_topk_prob[2 * b + 0] = 1.f / (1.f + __expf(-lg[i1]));
        g_topk_idx[2 * b + 1] = i2;
        g_topk_prob[2 * b + 1] = 1.f / (1.f + __expf(-lg[i2]));
    }
}

__global__ void moe_build() {
    __shared__ int cnt[NE], fill[NE], seg[NE];
    int tid = threadIdx.x;
    for (int i = tid; i < SLOT_CAP; i += blockDim.x) g_rows[i] = -1;
    if (tid < NE) { cnt[tid] = 0; fill[tid] = 0; }
    __syncthreads();
    for (int i = tid; i < NTOK * 2; i += blockDim.x)
        atomicAdd(&cnt[g_topk_idx[i]], 1);
    __syncthreads();
    if (tid == 0) {
        int off = 0, nt = 0;
        for (int e = 0; e < NE; e++) {
            seg[e] = off;
            int tiles = (cnt[e] + 127) >> 7;
            for (int t = 0; t < tiles; t++) {
                g_tile_e[nt] = e;
                g_tile_base[nt] = off + (t << 7);
                nt++;
            }
            off += tiles << 7;
        }
        g_num_tiles = nt;
    }
    __syncthreads();
    for (int i = tid; i < NTOK * 2; i += blockDim.x) {
        int e = g_topk_idx[i];
        int p = seg[e] + atomicAdd(&fill[e], 1);
        g_rows[p] = i >> 1;
        g_tok2slot[i] = p;
    }
}

// ---------------- GEMM1: h = silu(x@Wg)*(x@Wu), CTA 128m x 128n, 512 thr ----------------
// smem words: As[2][A_BUFW] | Bg[2][B_BUFW] | Bu[2][B_BUFW]
#define SMEM1_BYTES ((2 * A_BUFW + 4 * B_BUFW) * 4)

template <bool SHARED>
__global__ void __launch_bounds__(512)
moe_gemm1_mma(const float* __restrict__ x,
              const float* __restrict__ Wg,
              const float* __restrict__ Wu) {
    extern __shared__ uint32_t smw[];
    int by = blockIdx.y, e, base;
    if (SHARED) { e = 0; base = by * 128; }
    else {
        if (by >= g_num_tiles) return;
        e = g_tile_e[by];
        base = g_tile_base[by];
    }
    const int m0 = blockIdx.x * 128;
    const float* wg = Wg + (size_t)e * NH * NM;
    const float* wu = Wu + (size_t)e * NH * NM;

    const uint32_t sbase = smem_u32(smw);
    const int tid = threadIdx.x;
    const int lane = tid & 31, wid = tid >> 5;
    const int j = lane & 3, g = lane >> 2;
    const int wm = (wid & 3) * 32, wn = (wid >> 2) * 32;

    // LDSM per-lane address components
    const int a_row  = wm + ((lane >> 3) & 1) * 8 + (lane & 7);
    const int a_coff = (lane >> 4) * 4;
    const int b_krow = ((lane >> 3) & 1) * 8 + (lane & 7);
    const int b_coff = (wn >> 1) + (lane >> 4) * 4;

    // loader assignments
    const int row_a = tid & 127, q0 = tid >> 7;
    int tok = SHARED ? (base + row_a) : g_rows[base + row_a];
    const bool okA = (tok >= 0);
    const float* ax = x + (size_t)(okA ? tok : 0) * NH;
    const int bn = tid & 31, bk = tid >> 5;   // bk 0..15 (+16)

    float dg[2][4][4], du[2][4][4];
#pragma unroll
    for (int a1 = 0; a1 < 2; a1++)
#pragma unroll
        for (int b1 = 0; b1 < 4; b1++)
#pragma unroll
            for (int c1 = 0; c1 < 4; c1++) { dg[a1][b1][c1] = 0.f; du[a1][b1][c1] = 0.f; }

    const float4 z4 = make_float4(0.f, 0.f, 0.f, 0.f);
    float4 va0, va1, vg0, vu0, vg1, vu1;
    va0 = okA ? *(const float4*)(ax + 4 * q0) : z4;
    va1 = okA ? *(const float4*)(ax + 4 * q0 + 16) : z4;
    vg0 = *(const float4*)(wg + (size_t)bk * NM + m0 + bn * 4);
    vu0 = *(const float4*)(wu + (size_t)bk * NM + m0 + bn * 4);
    vg1 = *(const float4*)(wg + (size_t)(bk + 16) * NM + m0 + bn * 4);
    vu1 = *(const float4*)(wu + (size_t)(bk + 16) * NM + m0 + bn * 4);

    const int KC = NH / 32;
    int buf = 0;
    {
        *(uint2*)(smw + row_a * A_W + 2 * q0)     = make_uint2(pack2(va0.x, va0.y), pack2(va0.z, va0.w));
        *(uint2*)(smw + row_a * A_W + 2 * q0 + 8) = make_uint2(pack2(va1.x, va1.y), pack2(va1.z, va1.w));
        uint32_t* bg = smw + 2 * A_BUFW;
        uint32_t* bu = smw + 2 * A_BUFW + 2 * B_BUFW;
        *(uint2*)(bg + bk * B_W + bn * 2)        = make_uint2(pack2(vg0.x, vg0.y), pack2(vg0.z, vg0.w));
        *(uint2*)(bg + (bk + 16) * B_W + bn * 2) = make_uint2(pack2(vg1.x, vg1.y), pack2(vg1.z, vg1.w));
        *(uint2*)(bu + bk * B_W + bn * 2)        = make_uint2(pack2(vu0.x, vu0.y), pack2(vu0.z, vu0.w));
        *(uint2*)(bu + (bk + 16) * B_W + bn * 2) = make_uint2(pack2(vu1.x, vu1.y), pack2(vu1.z, vu1.w));
    }
    __syncthreads();

    for (int kc = 0; kc < KC; kc++) {
        if (kc + 1 < KC) {
            int k0 = (kc + 1) * 32;
            va0 = okA ? *(const float4*)(ax + k0 + 4 * q0) : z4;
            va1 = okA ? *(const float4*)(ax + k0 + 4 * q0 + 16) : z4;
            vg0 = *(const float4*)(wg + (size_t)(k0 + bk) * NM + m0 + bn * 4);
            vu0 = *(const float4*)(wu + (size_t)(k0 + bk) * NM + m0 + bn * 4);
            vg1 = *(const float4*)(wg + (size_t)(k0 + bk + 16) * NM + m0 + bn * 4);
            vu1 = *(const float4*)(wu + (size_t)(k0 + bk + 16) * NM + m0 + bn * 4);
        }
        const uint32_t asb = sbase + (buf * A_BUFW) * 4;
        const uint32_t bgb = sbase + (2 * A_BUFW + buf * B_BUFW) * 4;
        const uint32_t bub = sbase + (2 * A_BUFW + (2 + buf) * B_BUFW) * 4;
#pragma unroll
        for (int ks = 0; ks < 2; ks++) {
            uint32_t a[2][4];
#pragma unroll
            for (int mi = 0; mi < 2; mi++)
                ldsm4(a[mi], asb + ((a_row + mi * 16) * A_W + ks * 8 + a_coff) * 4);
            uint32_t fg[2][4], fu[2][4];
#pragma unroll
            for (int nip = 0; nip < 2; nip++) {
                uint32_t boff = ((b_krow + ks * 16) * B_W + b_coff + nip * 8) * 4;
                ldsm4t(fg[nip], bgb + boff);
                ldsm4t(fu[nip], bub + boff);
            }
#pragma unroll
            for (int ni = 0; ni < 4; ni++) {
                int nip = ni >> 1, o = (ni & 1) * 2;
#pragma unroll
                for (int mi = 0; mi < 2; mi++) {
                    mma16(dg[mi][ni], a[mi], fg[nip][o], fg[nip][o + 1]);
                    mma16(du[mi][ni], a[mi], fu[nip][o], fu[nip][o + 1]);
                }
            }
        }
        if (kc + 1 < KC) {
            buf ^= 1;
            uint32_t* as = smw + buf * A_BUFW;
            uint32_t* bg = smw + 2 * A_BUFW + buf * B_BUFW;
            uint32_t* bu = smw + 2 * A_BUFW + (2 + buf) * B_BUFW;
            *(uint2*)(as + row_a * A_W + 2 * q0)     = make_uint2(pack2(va0.x, va0.y), pack2(va0.z, va0.w));
            *(uint2*)(as + row_a * A_W + 2 * q0 + 8) = make_uint2(pack2(va1.x, va1.y), pack2(va1.z, va1.w));
            *(uint2*)(bg + bk * B_W + bn * 2)        = make_uint2(pack2(vg0.x, vg0.y), pack2(vg0.z, vg0.w));
            *(uint2*)(bg + (bk + 16) * B_W + bn * 2) = make_uint2(pack2(vg1.x, vg1.y), pack2(vg1.z, vg1.w));
            *(uint2*)(bu + bk * B_W + bn * 2)        = make_uint2(pack2(vu0.x, vu0.y), pack2(vu0.z, vu0.w));
            *(uint2*)(bu + (bk + 16) * B_W + bn * 2) = make_uint2(pack2(vu1.x, vu1.y), pack2(vu1.z, vu1.w));
            __syncthreads();
        }
    }

    const int hb = (SHARED ? SHARED_HBASE : 0) + base;
#pragma unroll
    for (int mi = 0; mi < 2; mi++)
#pragma unroll
        for (int ni = 0; ni < 4; ni++) {
            int r = hb + wm + 16 * mi + g;
            int col = m0 + wn + 8 * ni + 2 * j;
            float2 h0, h1;
            h0.x = silu_f(dg[mi][ni][0]) * du[mi][ni][0];
            h0.y = silu_f(dg[mi][ni][1]) * du[mi][ni][1];
            h1.x = silu_f(dg[mi][ni][2]) * du[mi][ni][2];
            h1.y = silu_f(dg[mi][ni][3]) * du[mi][ni][3];
            *(float2*)&g_hbuf[(size_t)r * NM + col] = h0;
            *(float2*)&g_hbuf[(size_t)(r + 8) * NM + col] = h1;
        }
}

// ---------------- GEMM2: out/eout = h @ Wd, CTA 128m x 128n, 512 thr ----------------
#define SMEM2_BYTES ((2 * A_BUFW + 2 * B_BUFW) * 4)

template <bool SHARED>
__global__ void __launch_bounds__(512)
moe_gemm2_mma(const float* __restrict__ Wd, float* __restrict__ out) {
    extern __shared__ uint32_t smw[];
    int by = blockIdx.y, e, base;
    if (SHARED) { e = 0; base = by * 128; }
    else {
        if (by >= g_num_tiles) return;
        e = g_tile_e[by];
        base = g_tile_base[by];
    }
    const int n0 = blockIdx.x * 128;
    const float* wd = Wd + (size_t)e * NM * NH;
    const int hb = (SHARED ? SHARED_HBASE : 0) + base;

    const uint32_t sbase = smem_u32(smw);
    const int tid = threadIdx.x;
    const int lane = tid & 31, wid = tid >> 5;
    const int j = lane & 3, g = lane >> 2;
    const int wm = (wid & 3) * 32, wn = (wid >> 2) * 32;

    const int a_row  = wm + ((lane >> 3) & 1) * 8 + (lane & 7);
    const int a_coff = (lane >> 4) * 4;
    const int b_krow = ((lane >> 3) & 1) * 8 + (lane & 7);
    const int b_coff = (wn >> 1) + (lane >> 4) * 4;

    const int row_a = tid & 127, q0 = tid >> 7;
    const float* ax = g_hbuf + (size_t)(hb + row_a) * NM;
    const int bn = tid & 31, bk = tid >> 5;

    float d[2][4][4];
#pragma unroll
    for (int a1 = 0; a1 < 2; a1++)
#pragma unroll
        for (int b1 = 0; b1 < 4; b1++)
#pragma unroll
            for (int c1 = 0; c1 < 4; c1++) d[a1][b1][c1] = 0.f;

    float4 va0, va1, vb0, vb1;
    va0 = *(const float4*)(ax + 4 * q0);
    va1 = *(const float4*)(ax + 4 * q0 + 16);
    vb0 = *(const float4*)(wd + (size_t)bk * NH + n0 + bn * 4);
    vb1 = *(const float4*)(wd + (size_t)(bk + 16) * NH + n0 + bn * 4);

    const int KC = NM / 32;
    int buf = 0;
    {
        *(uint2*)(smw + row_a * A_W + 2 * q0)     = make_uint2(pack2(va0.x, va0.y), pack2(va0.z, va0.w));
        *(uint2*)(smw + row_a * A_W + 2 * q0 + 8) = make_uint2(pack2(va1.x, va1.y), pack2(va1.z, va1.w));
        uint32_t* bs = smw + 2 * A_BUFW;
        *(uint2*)(bs + bk * B_W + bn * 2)        = make_uint2(pack2(vb0.x, vb0.y), pack2(vb0.z, vb0.w));
        *(uint2*)(bs + (bk + 16) * B_W + bn * 2) = make_uint2(pack2(vb1.x, vb1.y), pack2(vb1.z, vb1.w));
    }
    __syncthreads();

    for (int kc = 0; kc < KC; kc++) {
        if (kc + 1 < KC) {
            int k0 = (kc + 1) * 32;
            va0 = *(const float4*)(ax + k0 + 4 * q0);
            va1 = *(const float4*)(ax + k0 + 4 * q0 + 16);
            vb0 = *(const float4*)(wd + (size_t)(k0 + bk) * NH + n0 + bn * 4);
            vb1 = *(const float4*)(wd + (size_t)(k0 + bk + 16) * NH + n0 + bn * 4);
        }
        const uint32_t asb = sbase + (buf * A_BUFW) * 4;
        const uint32_t bsb = sbase + (2 * A_BUFW + buf * B_BUFW) * 4;
#pragma unroll
        for (int ks = 0; ks < 2; ks++) {
            uint32_t a[2][4];
#pragma unroll
            for (int mi = 0; mi < 2; mi++)
                ldsm4(a[mi], asb + ((a_row + mi * 16) * A_W + ks * 8 + a_coff) * 4);
            uint32_t fb[2][4];
#pragma unroll
            for (int nip = 0; nip < 2; nip++)
                ldsm4t(fb[nip], bsb + ((b_krow + ks * 16) * B_W + b_coff + nip * 8) * 4);
#pragma unroll
            for (int ni = 0; ni < 4; ni++) {
                int nip = ni >> 1, o = (ni & 1) * 2;
#pragma unroll
                for (int mi = 0; mi < 2; mi++)
                    mma16(d[mi][ni], a[mi], fb[nip][o], fb[nip][o + 1]);
            }
        }
        if (kc + 1 < KC) {
            buf ^= 1;
            uint32_t* as = smw + buf * A_BUFW;
            uint32_t* bs = smw + 2 * A_BUFW + buf * B_BUFW;
            *(uint2*)(as + row_a * A_W + 2 * q0)     = make_uint2(pack2(va0.x, va0.y), pack2(va0.z, va0.w));
            *(uint2*)(as + row_a * A_W + 2 * q0 + 8) = make_uint2(pack2(va1.x, va1.y), pack2(va1.z, va1.w));
            *(uint2*)(bs + bk * B_W + bn * 2)        = make_uint2(pack2(vb0.x, vb0.y), pack2(vb0.z, vb0.w));
            *(uint2*)(bs + (bk + 16) * B_W + bn * 2) = make_uint2(pack2(vb1.x, vb1.y), pack2(vb1.z, vb1.w));
            __syncthreads();
        }
    }

#pragma unroll
    for (int mi = 0; mi < 2; mi++)
#pragma unroll
        for (int ni = 0; ni < 4; ni++) {
            int r = base + wm + 16 * mi + g;
            int col = n0 + wn + 8 * ni + 2 * j;
            float* dst0 = SHARED ? (out + (size_t)r * NH + col)
                                 : (g_eout + (size_t)r * NH + col);
            float* dst1 = SHARED ? (out + (size_t)(r + 8) * NH + col)
                                 : (g_eout + (size_t)(r + 8) * NH + col);
            *(float2*)dst0 = make_float2(d[mi][ni][0], d[mi][ni][1]);
            *(float2*)dst1 = make_float2(d[mi][ni][2], d[mi][ni][3]);
        }
}

// ---------------- combine ----------------
__global__ void moe_combine(float* __restrict__ out) {
    int t = blockIdx.x;
    int h = threadIdx.x * 4;
    int s0 = g_tok2slot[2 * t + 0], s1 = g_tok2slot[2 * t + 1];
    float p0 = g_topk_prob[2 * t + 0], p1 = g_topk_prob[2 * t + 1];
    float4 o = *(float4*)(out + (size_t)t * NH + h);
    float4 a = *(const float4*)(g_eout + (size_t)s0 * NH + h);
    float4 b = *(const float4*)(g_eout + (size_t)s1 * NH + h);
    o.x += p0 * a.x + p1 * b.x;
    o.y += p0 * a.y + p1 * b.y;
    o.z += p0 * a.z + p1 * b.z;
    o.w += p0 * a.w + p1 * b.w;
    *(float4*)(out + (size_t)t * NH + h) = o;
}

// ---------------- launch ----------------
extern "C" void kernel_launch(void* const* d_in, const int* in_sizes, int n_in,
                              void* d_out, int out_size) {
    const float* x    = (const float*)d_in[0];
    const float* gw   = (const float*)d_in[1];
    const float* beta = (const float*)d_in[2];
    const float* gpw  = (const float*)d_in[3];
    const float* upw  = (const float*)d_in[4];
    const float* dpw  = (const float*)d_in[5];
    const float* sgw  = (const float*)d_in[6];
    const float* suw  = (const float*)d_in[7];
    const float* sdw  = (const float*)d_in[8];
    float* out = (float*)d_out;

    cudaFuncSetAttribute(moe_gemm1_mma<false>, cudaFuncAttributeMaxDynamicSharedMemorySize, SMEM1_BYTES);
    cudaFuncSetAttribute(moe_gemm1_mma<true>,  cudaFuncAttributeMaxDynamicSharedMemorySize, SMEM1_BYTES);
    cudaFuncSetAttribute(moe_gemm2_mma<false>, cudaFuncAttributeMaxDynamicSharedMemorySize, SMEM2_BYTES);
    cudaFuncSetAttribute(moe_gemm2_mma<true>,  cudaFuncAttributeMaxDynamicSharedMemorySize, SMEM2_BYTES);

    moe_route<<<NTOK, 256>>>(x, gw, beta);
    moe_build<<<1, 512>>>();

    moe_gemm1_mma<false><<<dim3(NM / 128, 40), 512, SMEM1_BYTES>>>(x, gpw, upw);
    moe_gemm1_mma<true> <<<dim3(NM / 128, NTOK / 128), 512, SMEM1_BYTES>>>(x, sgw, suw);

    moe_gemm2_mma<true> <<<dim3(NH / 128, NTOK / 128), 512, SMEM2_BYTES>>>(sdw, out);
    moe_gemm2_mma<false><<<dim3(NH / 128, 40), 512, SMEM2_BYTES>>>(dpw, out);

    moe_combine<<<NTOK, 256>>>(out);
}

// round 13
// speedup vs baseline: 2.4069x; 1.3906x over previous
#include <cuda_runtime.h>
#include <cuda_fp16.h>
#include <cstdint>

#define NE   8
#define NH   1024
#define NM   2048
#define NTOK 2048
#define SLOT_CAP     6144
#define SHARED_HBASE 6144
#define HROWS        8192
#define MAX_TILES    48

// fp16 smem layouts (word = 4B = 2 fp16)
#define A_W    20
#define A_BUFW 2560    // 128 * 20
#define B_W    68
#define B_BUFW 2176    // 32 * 68
#define SW1    (A_BUFW + 2 * B_BUFW)   // gemm1 stage words = 6912
#define SW2    (A_BUFW + B_BUFW)       // gemm2 stage words = 4736
#define SMEM1_BYTES (4 * SW1 * 4)      // 110592
#define SMEM2_BYTES (4 * SW2 * 4)      // 75776

// ---------------- device scratch ----------------
__device__ int    g_rows[SLOT_CAP];
__device__ int    g_tile_e[MAX_TILES];
__device__ int    g_tile_base[MAX_TILES];
__device__ int    g_num_tiles;
__device__ int    g_topk_idx[NTOK * 2];
__device__ float  g_topk_prob[NTOK * 2];
__device__ int    g_tok2slot[NTOK * 2];
__device__ __half g_hbuf[(size_t)HROWS * NM];       // fp16 h
__device__ float  g_eout[(size_t)SLOT_CAP * NH];
__device__ __half g_xh[(size_t)NTOK * NH];
__device__ __half g_wgh[(size_t)NE * NH * NM];
__device__ __half g_wuh[(size_t)NE * NH * NM];
__device__ __half g_wdh[(size_t)NE * NM * NH];
__device__ __half g_sgh[(size_t)NH * NM];
__device__ __half g_suh[(size_t)NH * NM];
__device__ __half g_sdh[(size_t)NM * NH];

// ---------------- helpers ----------------
__device__ __forceinline__ uint32_t smem_u32(const void* p) {
    uint32_t a;
    asm("{ .reg .u64 t; cvta.to.shared.u64 t, %1; cvt.u32.u64 %0, t; }" : "=r"(a) : "l"(p));
    return a;
}
__device__ __forceinline__ uint32_t pack2(float lo, float hi) {
    __half2 h = __floats2half2_rn(lo, hi);
    return *(uint32_t*)&h;
}
__device__ __forceinline__ float silu_f(float v) { return v / (1.0f + __expf(-v)); }

__device__ __forceinline__ void cpa16(uint32_t dst, const void* src, int szbytes) {
    asm volatile("cp.async.cg.shared.global [%0], [%1], 16, %2;"
        :: "r"(dst), "l"(src), "r"(szbytes) : "memory");
}
#define CP_COMMIT() asm volatile("cp.async.commit_group;" ::: "memory")
#define CP_WAIT2()  asm volatile("cp.async.wait_group 2;" ::: "memory")

__device__ __forceinline__ void ldsm4(uint32_t* r, uint32_t addr) {
    asm volatile("ldmatrix.sync.aligned.m8n8.x4.shared.b16 {%0,%1,%2,%3}, [%4];"
        : "=r"(r[0]), "=r"(r[1]), "=r"(r[2]), "=r"(r[3]) : "r"(addr));
}
__device__ __forceinline__ void ldsm4t(uint32_t* r, uint32_t addr) {
    asm volatile("ldmatrix.sync.aligned.m8n8.x4.trans.shared.b16 {%0,%1,%2,%3}, [%4];"
        : "=r"(r[0]), "=r"(r[1]), "=r"(r[2]), "=r"(r[3]) : "r"(addr));
}
__device__ __forceinline__ void mma16(float* d, const uint32_t* a, uint32_t b0, uint32_t b1) {
    asm volatile(
        "mma.sync.aligned.m16n8k16.row.col.f32.f16.f16.f32 "
        "{%0,%1,%2,%3},{%4,%5,%6,%7},{%8,%9},{%0,%1,%2,%3};"
        : "+f"(d[0]), "+f"(d[1]), "+f"(d[2]), "+f"(d[3])
        : "r"(a[0]), "r"(a[1]), "r"(a[2]), "r"(a[3]), "r"(b0), "r"(b1));
}

// ---------------- fp32 -> fp16 bulk convert (8 elems/thread) ----------------
__global__ void cvt8(const float4* __restrict__ src, uint4* __restrict__ dst, int n8) {
    int i = blockIdx.x * blockDim.x + threadIdx.x;
    if (i >= n8) return;
    float4 a = src[2 * i], b = src[2 * i + 1];
    dst[i] = make_uint4(pack2(a.x, a.y), pack2(a.z, a.w),
                        pack2(b.x, b.y), pack2(b.z, b.w));
}

// ---------------- routing (also emits fp16 x) ----------------
__global__ void moe_route(const float* __restrict__ x,
                          const float* __restrict__ gw,
                          const float* __restrict__ beta) {
    int b = blockIdx.x;
    const float* xr = x + (size_t)b * NH;
    float acc[NE];
#pragma unroll
    for (int e = 0; e < NE; e++) acc[e] = 0.f;
    for (int h = threadIdx.x; h < NH; h += 256) {
        float xv = xr[h];
        g_xh[(size_t)b * NH + h] = __float2half(xv);
#pragma unroll
        for (int e = 0; e < NE; e++) acc[e] += xv * gw[e * NH + h];
    }
#pragma unroll
    for (int off = 16; off > 0; off >>= 1)
#pragma unroll
        for (int e = 0; e < NE; e++)
            acc[e] += __shfl_down_sync(0xFFFFFFFFu, acc[e], off);
    __shared__ float part[8][NE];
    int lane = threadIdx.x & 31, warp = threadIdx.x >> 5;
    if (lane == 0)
#pragma unroll
        for (int e = 0; e < NE; e++) part[warp][e] = acc[e];
    __syncthreads();
    if (threadIdx.x == 0) {
        float lg[NE];
#pragma unroll
        for (int e = 0; e < NE; e++) {
            float s = 0.f;
#pragma unroll
            for (int w = 0; w < 8; w++) s += part[w][e];
            lg[e] = s;
        }
        int i1 = 0; float b1 = -1e30f;
#pragma unroll
        for (int e = 0; e < NE; e++) {
            float v = lg[e] + beta[e];
            if (v > b1) { b1 = v; i1 = e; }
        }
        int i2 = -1; float b2 = -1e30f;
#pragma unroll
        for (int e = 0; e < NE; e++) {
            if (e == i1) continue;
            float v = lg[e] + beta[e];
            if (v > b2) { b2 = v; i2 = e; }
        }
        g_topk_idx[2 * b + 0] = i1;
        g_topk_prob[2 * b + 0] = 1.f / (1.f + __expf(-lg[i1]));
        g_topk_idx[2 * b + 1] = i2;
        g_topk_prob[2 * b + 1] = 1.f / (1.f + __expf(-lg[i2]));
    }
}

__global__ void moe_build() {
    __shared__ int cnt[NE], fill[NE], seg[NE];
    int tid = threadIdx.x;
    for (int i = tid; i < SLOT_CAP; i += blockDim.x) g_rows[i] = -1;
    if (tid < NE) { cnt[tid] = 0; fill[tid] = 0; }
    __syncthreads();
    for (int i = tid; i < NTOK * 2; i += blockDim.x)
        atomicAdd(&cnt[g_topk_idx[i]], 1);
    __syncthreads();
    if (tid == 0) {
        int off = 0, nt = 0;
        for (int e = 0; e < NE; e++) {
            seg[e] = off;
            int tiles = (cnt[e] + 127) >> 7;
            for (int t = 0; t < tiles; t++) {
                g_tile_e[nt] = e;
                g_tile_base[nt] = off + (t << 7);
                nt++;
            }
            off += tiles << 7;
        }
        g_num_tiles = nt;
    }
    __syncthreads();
    for (int i = tid; i < NTOK * 2; i += blockDim.x) {
        int e = g_topk_idx[i];
        int p = seg[e] + atomicAdd(&fill[e], 1);
        g_rows[p] = i >> 1;
        g_tok2slot[i] = p;
    }
}

// ---------------- GEMM1: h = silu(x@Wg)*(x@Wu), CTA 128m x 128n, 512 thr ----------------
template <bool SHARED>
__global__ void __launch_bounds__(512)
moe_gemm1_mma(const __half* __restrict__ xh,
              const __half* __restrict__ Wg,
              const __half* __restrict__ Wu) {
    extern __shared__ uint32_t smw[];
    int by = blockIdx.y, e, base;
    if (SHARED) { e = 0; base = by * 128; }
    else {
        if (by >= g_num_tiles) return;
        e = g_tile_e[by];
        base = g_tile_base[by];
    }
    const int m0 = blockIdx.x * 128;
    const __half* wg = Wg + (size_t)e * NH * NM;
    const __half* wu = Wu + (size_t)e * NH * NM;

    const uint32_t sbase = smem_u32(smw);
    const int tid = threadIdx.x;
    const int lane = tid & 31, wid = tid >> 5;
    const int j = lane & 3, g = lane >> 2;
    const int wm = (wid & 3) * 32, wn = (wid >> 2) * 32;

    const int a_row  = wm + ((lane >> 3) & 1) * 8 + (lane & 7);
    const int a_coff = (lane >> 4) * 4;
    const int b_krow = ((lane >> 3) & 1) * 8 + (lane & 7);
    const int b_coff = (wn >> 1) + (lane >> 4) * 4;

    // loaders
    const int row_a = tid & 127, qa = tid >> 7;          // A: 16B chunk qa of row
    int tok = SHARED ? (base + row_a) : g_rows[base + row_a];
    const bool okA = (tok >= 0);
    const int a_sz = okA ? 16 : 0;
    const __half* ax = xh + (size_t)(okA ? tok : 0) * NH + 8 * qa;
    const int bkk = tid >> 4, bc = tid & 15;             // B: row bkk, chunk bc
    const uint32_t a_dst = sbase + (row_a * A_W + 4 * qa) * 4;
    const uint32_t bg_dst = sbase + (A_BUFW + bkk * B_W + 4 * bc) * 4;
    const uint32_t bu_dst = bg_dst + B_BUFW * 4;
    const __half* wgp = wg + (size_t)bkk * NM + m0 + 8 * bc;
    const __half* wup = wu + (size_t)bkk * NM + m0 + 8 * bc;

    float dg[2][4][4], du[2][4][4];
#pragma unroll
    for (int a1 = 0; a1 < 2; a1++)
#pragma unroll
        for (int b1 = 0; b1 < 4; b1++)
#pragma unroll
            for (int c1 = 0; c1 < 4; c1++) { dg[a1][b1][c1] = 0.f; du[a1][b1][c1] = 0.f; }

    const int KC = NH / 32;
    // prologue: stages 0..2
#pragma unroll
    for (int s = 0; s < 3; s++) {
        uint32_t so = s * SW1 * 4;
        cpa16(a_dst + so, ax + s * 32, a_sz);
        cpa16(bg_dst + so, wgp + (size_t)s * 32 * NM, 16);
        cpa16(bu_dst + so, wup + (size_t)s * 32 * NM, 16);
        CP_COMMIT();
    }

    for (int kc = 0; kc < KC; kc++) {
        CP_WAIT2();
        __syncthreads();
        const int st = kc & 3;
        const uint32_t asb = sbase + (st * SW1) * 4;
        const uint32_t bgb = asb + A_BUFW * 4;
        const uint32_t bub = bgb + B_BUFW * 4;
#pragma unroll
        for (int ks = 0; ks < 2; ks++) {
            uint32_t a[2][4];
#pragma unroll
            for (int mi = 0; mi < 2; mi++)
                ldsm4(a[mi], asb + ((a_row + mi * 16) * A_W + ks * 8 + a_coff) * 4);
            uint32_t fg[2][4], fu[2][4];
#pragma unroll
            for (int nip = 0; nip < 2; nip++) {
                uint32_t boff = ((b_krow + ks * 16) * B_W + b_coff + nip * 8) * 4;
                ldsm4t(fg[nip], bgb + boff);
                ldsm4t(fu[nip], bub + boff);
            }
#pragma unroll
            for (int ni = 0; ni < 4; ni++) {
                int nip = ni >> 1, o = (ni & 1) * 2;
#pragma unroll
                for (int mi = 0; mi < 2; mi++) {
                    mma16(dg[mi][ni], a[mi], fg[nip][o], fg[nip][o + 1]);
                    mma16(du[mi][ni], a[mi], fu[nip][o], fu[nip][o + 1]);
                }
            }
        }
        int nk = kc + 3;
        if (nk < KC) {
            uint32_t so = (nk & 3) * SW1 * 4;
            cpa16(a_dst + so, ax + nk * 32, a_sz);
            cpa16(bg_dst + so, wgp + (size_t)nk * 32 * NM, 16);
            cpa16(bu_dst + so, wup + (size_t)nk * 32 * NM, 16);
        }
        CP_COMMIT();
    }

    const int hb = (SHARED ? SHARED_HBASE : 0) + base;
    uint32_t* h32 = (uint32_t*)g_hbuf;
#pragma unroll
    for (int mi = 0; mi < 2; mi++)
#pragma unroll
        for (int ni = 0; ni < 4; ni++) {
            int r = hb + wm + 16 * mi + g;
            int cw = (m0 + wn + 8 * ni + 2 * j) >> 1;   // word column
            h32[(size_t)r * (NM / 2) + cw] =
                pack2(silu_f(dg[mi][ni][0]) * du[mi][ni][0],
                      silu_f(dg[mi][ni][1]) * du[mi][ni][1]);
            h32[(size_t)(r + 8) * (NM / 2) + cw] =
                pack2(silu_f(dg[mi][ni][2]) * du[mi][ni][2],
                      silu_f(dg[mi][ni][3]) * du[mi][ni][3]);
        }
}

// ---------------- GEMM2: out/eout = h @ Wd, CTA 128m x 128n, 512 thr ----------------
template <bool SHARED>
__global__ void __launch_bounds__(512)
moe_gemm2_mma(const __half* __restrict__ Wd, float* __restrict__ out) {
    extern __shared__ uint32_t smw[];
    int by = blockIdx.y, e, base;
    if (SHARED) { e = 0; base = by * 128; }
    else {
        if (by >= g_num_tiles) return;
        e = g_tile_e[by];
        base = g_tile_base[by];
    }
    const int n0 = blockIdx.x * 128;
    const __half* wd = Wd + (size_t)e * NM * NH;
    const int hb = (SHARED ? SHARED_HBASE : 0) + base;

    const uint32_t sbase = smem_u32(smw);
    const int tid = threadIdx.x;
    const int lane = tid & 31, wid = tid >> 5;
    const int j = lane & 3, g = lane >> 2;
    const int wm = (wid & 3) * 32, wn = (wid >> 2) * 32;

    const int a_row  = wm + ((lane >> 3) & 1) * 8 + (lane & 7);
    const int a_coff = (lane >> 4) * 4;
    const int b_krow = ((lane >> 3) & 1) * 8 + (lane & 7);
    const int b_coff = (wn >> 1) + (lane >> 4) * 4;

    const int row_a = tid & 127, qa = tid >> 7;
    const __half* ax = g_hbuf + (size_t)(hb + row_a) * NM + 8 * qa;
    const int bkk = tid >> 4, bc = tid & 15;
    const uint32_t a_dst = sbase + (row_a * A_W + 4 * qa) * 4;
    const uint32_t b_dst = sbase + (A_BUFW + bkk * B_W + 4 * bc) * 4;
    const __half* wdp = wd + (size_t)bkk * NH + n0 + 8 * bc;

    float d[2][4][4];
#pragma unroll
    for (int a1 = 0; a1 < 2; a1++)
#pragma unroll
        for (int b1 = 0; b1 < 4; b1++)
#pragma unroll
            for (int c1 = 0; c1 < 4; c1++) d[a1][b1][c1] = 0.f;

    const int KC = NM / 32;
#pragma unroll
    for (int s = 0; s < 3; s++) {
        uint32_t so = s * SW2 * 4;
        cpa16(a_dst + so, ax + s * 32, 16);
        cpa16(b_dst + so, wdp + (size_t)s * 32 * NH, 16);
        CP_COMMIT();
    }

    for (int kc = 0; kc < KC; kc++) {
        CP_WAIT2();
        __syncthreads();
        const int st = kc & 3;
        const uint32_t asb = sbase + (st * SW2) * 4;
        const uint32_t bsb = asb + A_BUFW * 4;
#pragma unroll
        for (int ks = 0; ks < 2; ks++) {
            uint32_t a[2][4];
#pragma unroll
            for (int mi = 0; mi < 2; mi++)
                ldsm4(a[mi], asb + ((a_row + mi * 16) * A_W + ks * 8 + a_coff) * 4);
            uint32_t fb[2][4];
#pragma unroll
            for (int nip = 0; nip < 2; nip++)
                ldsm4t(fb[nip], bsb + ((b_krow + ks * 16) * B_W + b_coff + nip * 8) * 4);
#pragma unroll
            for (int ni = 0; ni < 4; ni++) {
                int nip = ni >> 1, o = (ni & 1) * 2;
#pragma unroll
                for (int mi = 0; mi < 2; mi++)
                    mma16(d[mi][ni], a[mi], fb[nip][o], fb[nip][o + 1]);
            }
        }
        int nk = kc + 3;
        if (nk < KC) {
            uint32_t so = (nk & 3) * SW2 * 4;
            cpa16(a_dst + so, ax + nk * 32, 16);
            cpa16(b_dst + so, wdp + (size_t)nk * 32 * NH, 16);
        }
        CP_COMMIT();
    }

#pragma unroll
    for (int mi = 0; mi < 2; mi++)
#pragma unroll
        for (int ni = 0; ni < 4; ni++) {
            int r = base + wm + 16 * mi + g;
            int col = n0 + wn + 8 * ni + 2 * j;
            float* dst0 = SHARED ? (out + (size_t)r * NH + col)
                                 : (g_eout + (size_t)r * NH + col);
            float* dst1 = SHARED ? (out + (size_t)(r + 8) * NH + col)
                                 : (g_eout + (size_t)(r + 8) * NH + col);
            *(float2*)dst0 = make_float2(d[mi][ni][0], d[mi][ni][1]);
            *(float2*)dst1 = make_float2(d[mi][ni][2], d[mi][ni][3]);
        }
}

// ---------------- combine ----------------
__global__ void moe_combine(float* __restrict__ out) {
    int t = blockIdx.x;
    int h = threadIdx.x * 4;
    int s0 = g_tok2slot[2 * t + 0], s1 = g_tok2slot[2 * t + 1];
    float p0 = g_topk_prob[2 * t + 0], p1 = g_topk_prob[2 * t + 1];
    float4 o = *(float4*)(out + (size_t)t * NH + h);
    float4 a = *(const float4*)(g_eout + (size_t)s0 * NH + h);
    float4 b = *(const float4*)(g_eout + (size_t)s1 * NH + h);
    o.x += p0 * a.x + p1 * b.x;
    o.y += p0 * a.y + p1 * b.y;
    o.z += p0 * a.z + p1 * b.z;
    o.w += p0 * a.w + p1 * b.w;
    *(float4*)(out + (size_t)t * NH + h) = o;
}

// ---------------- launch ----------------
static __half* dev_sym(const void* symaddr) { return (__half*)symaddr; }

extern "C" void kernel_launch(void* const* d_in, const int* in_sizes, int n_in,
                              void* d_out, int out_size) {
    const float* x    = (const float*)d_in[0];
    const float* gw   = (const float*)d_in[1];
    const float* beta = (const float*)d_in[2];
    const float* gpw  = (const float*)d_in[3];
    const float* upw  = (const float*)d_in[4];
    const float* dpw  = (const float*)d_in[5];
    const float* sgw  = (const float*)d_in[6];
    const float* suw  = (const float*)d_in[7];
    const float* sdw  = (const float*)d_in[8];
    float* out = (float*)d_out;

    static __half *wgh = nullptr, *wuh = nullptr, *wdh = nullptr,
                  *sgh = nullptr, *suh = nullptr, *sdh = nullptr, *xh = nullptr;
    if (!wgh) {
        void* p;
        cudaGetSymbolAddress(&p, g_wgh); wgh = (__half*)p;
        cudaGetSymbolAddress(&p, g_wuh); wuh = (__half*)p;
        cudaGetSymbolAddress(&p, g_wdh); wdh = (__half*)p;
        cudaGetSymbolAddress(&p, g_sgh); sgh = (__half*)p;
        cudaGetSymbolAddress(&p, g_suh); suh = (__half*)p;
        cudaGetSymbolAddress(&p, g_sdh); sdh = (__half*)p;
        cudaGetSymbolAddress(&p, g_xh);  xh  = (__half*)p;
        cudaFuncSetAttribute(moe_gemm1_mma<false>, cudaFuncAttributeMaxDynamicSharedMemorySize, SMEM1_BYTES);
        cudaFuncSetAttribute(moe_gemm1_mma<true>,  cudaFuncAttributeMaxDynamicSharedMemorySize, SMEM1_BYTES);
        cudaFuncSetAttribute(moe_gemm2_mma<false>, cudaFuncAttributeMaxDynamicSharedMemorySize, SMEM2_BYTES);
        cudaFuncSetAttribute(moe_gemm2_mma<true>,  cudaFuncAttributeMaxDynamicSharedMemorySize, SMEM2_BYTES);
    }

    const int NBIG = NE * NH * NM / 8;      // 2M uint4-groups
    const int NSML = NH * NM / 8;           // 256K
    cvt8<<<(NBIG + 255) / 256, 256>>>((const float4*)gpw, (uint4*)wgh, NBIG);
    cvt8<<<(NBIG + 255) / 256, 256>>>((const float4*)upw, (uint4*)wuh, NBIG);
    cvt8<<<(NBIG + 255) / 256, 256>>>((const float4*)dpw, (uint4*)wdh, NBIG);
    cvt8<<<(NSML + 255) / 256, 256>>>((const float4*)sgw, (uint4*)sgh, NSML);
    cvt8<<<(NSML + 255) / 256, 256>>>((const float4*)suw, (uint4*)suh, NSML);
    cvt8<<<(NSML + 255) / 256, 256>>>((const float4*)sdw, (uint4*)sdh, NSML);

    moe_route<<<NTOK, 256>>>(x, gw, beta);
    moe_build<<<1, 512>>>();

    moe_gemm1_mma<false><<<dim3(NM / 128, 40), 512, SMEM1_BYTES>>>(xh, wgh, wuh);
    moe_gemm1_mma<true> <<<dim3(NM / 128, NTOK / 128), 512, SMEM1_BYTES>>>(xh, sgh, suh);

    moe_gemm2_mma<true> <<<dim3(NH / 128, NTOK / 128), 512, SMEM2_BYTES>>>(sdh, out);
    moe_gemm2_mma<false><<<dim3(NH / 128, 40), 512, SMEM2_BYTES>>>(wdh, out);

    moe_combine<<<NTOK, 256>>>(out);
}

// round 14
// speedup vs baseline: 2.4253x; 1.0076x over previous
#include <cuda_runtime.h>
#include <cuda_fp16.h>
#include <cstdint>

#define NE   8
#define NH   1024
#define NM   2048
#define NTOK 2048
#define SLOT_CAP     6144
#define SHARED_HBASE 6144
#define HROWS        8192
#define MAX_TILES    48

// fp16 smem layouts (word = 4B = 2 fp16)
#define A_W    20
#define A_BUFW 2560    // 128 * 20
#define B_W    68
#define B_BUFW 2176    // 32 * 68
#define SW1    (A_BUFW + 2 * B_BUFW)   // gemm1 stage words = 6912
#define SW2    (A_BUFW + B_BUFW)       // gemm2 stage words = 4736
#define SMEM1_BYTES (4 * SW1 * 4)      // 110592
#define SMEM2_BYTES (4 * SW2 * 4)      // 75776

// ---------------- device scratch ----------------
__device__ int    g_rows[SLOT_CAP];
__device__ int    g_tile_e[MAX_TILES];
__device__ int    g_tile_base[MAX_TILES];
__device__ int    g_num_tiles;
__device__ int    g_topk_idx[NTOK * 2];
__device__ float  g_topk_prob[NTOK * 2];
__device__ int    g_tok2slot[NTOK * 2];
__device__ __half g_hbuf[(size_t)HROWS * NM];
__device__ float  g_eout[(size_t)SLOT_CAP * NH];
__device__ __half g_xh[(size_t)NTOK * NH];
__device__ __half g_wgh[(size_t)NE * NH * NM];
__device__ __half g_wuh[(size_t)NE * NH * NM];
__device__ __half g_wdh[(size_t)NE * NM * NH];
__device__ __half g_sgh[(size_t)NH * NM];
__device__ __half g_suh[(size_t)NH * NM];
__device__ __half g_sdh[(size_t)NM * NH];

// ---------------- helpers ----------------
__device__ __forceinline__ uint32_t smem_u32(const void* p) {
    uint32_t a;
    asm("{ .reg .u64 t; cvta.to.shared.u64 t, %1; cvt.u32.u64 %0, t; }" : "=r"(a) : "l"(p));
    return a;
}
__device__ __forceinline__ uint32_t pack2(float lo, float hi) {
    __half2 h = __floats2half2_rn(lo, hi);
    return *(uint32_t*)&h;
}
__device__ __forceinline__ float silu_f(float v) { return v / (1.0f + __expf(-v)); }

__device__ __forceinline__ void cpa16(uint32_t dst, const void* src, int szbytes) {
    asm volatile("cp.async.cg.shared.global [%0], [%1], 16, %2;"
        :: "r"(dst), "l"(src), "r"(szbytes) : "memory");
}
#define CP_COMMIT() asm volatile("cp.async.commit_group;" ::: "memory")
#define CP_WAIT2()  asm volatile("cp.async.wait_group 2;" ::: "memory")

__device__ __forceinline__ void ldsm4(uint32_t* r, uint32_t addr) {
    asm volatile("ldmatrix.sync.aligned.m8n8.x4.shared.b16 {%0,%1,%2,%3}, [%4];"
        : "=r"(r[0]), "=r"(r[1]), "=r"(r[2]), "=r"(r[3]) : "r"(addr));
}
__device__ __forceinline__ void ldsm4t(uint32_t* r, uint32_t addr) {
    asm volatile("ldmatrix.sync.aligned.m8n8.x4.trans.shared.b16 {%0,%1,%2,%3}, [%4];"
        : "=r"(r[0]), "=r"(r[1]), "=r"(r[2]), "=r"(r[3]) : "r"(addr));
}
__device__ __forceinline__ void mma16(float* d, const uint32_t* a, uint32_t b0, uint32_t b1) {
    asm volatile(
        "mma.sync.aligned.m16n8k16.row.col.f32.f16.f16.f32 "
        "{%0,%1,%2,%3},{%4,%5,%6,%7},{%8,%9},{%0,%1,%2,%3};"
        : "+f"(d[0]), "+f"(d[1]), "+f"(d[2]), "+f"(d[3])
        : "r"(a[0]), "r"(a[1]), "r"(a[2]), "r"(a[3]), "r"(b0), "r"(b1));
}

// ---------------- fp32 -> fp16 bulk convert (8 elems/thread) ----------------
__global__ void cvt8(const float4* __restrict__ src, uint4* __restrict__ dst, int n8) {
    int i = blockIdx.x * blockDim.x + threadIdx.x;
    if (i >= n8) return;
    float4 a = src[2 * i], b = src[2 * i + 1];
    dst[i] = make_uint4(pack2(a.x, a.y), pack2(a.z, a.w),
                        pack2(b.x, b.y), pack2(b.z, b.w));
}

// ---------------- routing (also emits fp16 x) ----------------
__global__ void moe_route(const float* __restrict__ x,
                          const float* __restrict__ gw,
                          const float* __restrict__ beta) {
    int b = blockIdx.x;
    const float* xr = x + (size_t)b * NH;
    float acc[NE];
#pragma unroll
    for (int e = 0; e < NE; e++) acc[e] = 0.f;
    for (int h = threadIdx.x; h < NH; h += 256) {
        float xv = xr[h];
        g_xh[(size_t)b * NH + h] = __float2half(xv);
#pragma unroll
        for (int e = 0; e < NE; e++) acc[e] += xv * gw[e * NH + h];
    }
#pragma unroll
    for (int off = 16; off > 0; off >>= 1)
#pragma unroll
        for (int e = 0; e < NE; e++)
            acc[e] += __shfl_down_sync(0xFFFFFFFFu, acc[e], off);
    __shared__ float part[8][NE];
    int lane = threadIdx.x & 31, warp = threadIdx.x >> 5;
    if (lane == 0)
#pragma unroll
        for (int e = 0; e < NE; e++) part[warp][e] = acc[e];
    __syncthreads();
    if (threadIdx.x == 0) {
        float lg[NE];
#pragma unroll
        for (int e = 0; e < NE; e++) {
            float s = 0.f;
#pragma unroll
            for (int w = 0; w < 8; w++) s += part[w][e];
            lg[e] = s;
        }
        int i1 = 0; float b1 = -1e30f;
#pragma unroll
        for (int e = 0; e < NE; e++) {
            float v = lg[e] + beta[e];
            if (v > b1) { b1 = v; i1 = e; }
        }
        int i2 = -1; float b2 = -1e30f;
#pragma unroll
        for (int e = 0; e < NE; e++) {
            if (e == i1) continue;
            float v = lg[e] + beta[e];
            if (v > b2) { b2 = v; i2 = e; }
        }
        g_topk_idx[2 * b + 0] = i1;
        g_topk_prob[2 * b + 0] = 1.f / (1.f + __expf(-lg[i1]));
        g_topk_idx[2 * b + 1] = i2;
        g_topk_prob[2 * b + 1] = 1.f / (1.f + __expf(-lg[i2]));
    }
}

__global__ void moe_build() {
    __shared__ int cnt[NE], fill[NE], seg[NE];
    int tid = threadIdx.x;
    for (int i = tid; i < SLOT_CAP; i += blockDim.x) g_rows[i] = -1;
    if (tid < NE) { cnt[tid] = 0; fill[tid] = 0; }
    __syncthreads();
    for (int i = tid; i < NTOK * 2; i += blockDim.x)
        atomicAdd(&cnt[g_topk_idx[i]], 1);
    __syncthreads();
    if (tid == 0) {
        int off = 0, nt = 0;
        for (int e = 0; e < NE; e++) {
            seg[e] = off;
            int tiles = (cnt[e] + 127) >> 7;
            for (int t = 0; t < tiles; t++) {
                g_tile_e[nt] = e;
                g_tile_base[nt] = off + (t << 7);
                nt++;
            }
            off += tiles << 7;
        }
        g_num_tiles = nt;
    }
    __syncthreads();
    for (int i = tid; i < NTOK * 2; i += blockDim.x) {
        int e = g_topk_idx[i];
        int p = seg[e] + atomicAdd(&fill[e], 1);
        g_rows[p] = i >> 1;
        g_tok2slot[i] = p;
    }
}

// ---------------- GEMM1: h = silu(x@Wg)*(x@Wu), CTA 128m x 128n, 512 thr ----------------
template <bool SHARED>
__global__ void __launch_bounds__(512)
moe_gemm1_mma(const __half* __restrict__ xh,
              const __half* __restrict__ Wg,
              const __half* __restrict__ Wu) {
    extern __shared__ uint32_t smw[];
    int by = blockIdx.y, e, base;
    if (SHARED) { e = 0; base = by * 128; }
    else {
        if (by >= g_num_tiles) return;
        e = g_tile_e[by];
        base = g_tile_base[by];
    }
    const int m0 = blockIdx.x * 128;
    const __half* wg = Wg + (size_t)e * NH * NM;
    const __half* wu = Wu + (size_t)e * NH * NM;

    const uint32_t sbase = smem_u32(smw);
    const int tid = threadIdx.x;
    const int lane = tid & 31, wid = tid >> 5;
    const int j = lane & 3, g = lane >> 2;
    const int wm = (wid & 3) * 32, wn = (wid >> 2) * 32;

    const int a_row  = wm + ((lane >> 3) & 1) * 8 + (lane & 7);
    const int a_coff = (lane >> 4) * 4;
    const int b_krow = ((lane >> 3) & 1) * 8 + (lane & 7);
    const int b_coff = (wn >> 1) + (lane >> 4) * 4;

    const int row_a = tid & 127, qa = tid >> 7;
    int tok = SHARED ? (base + row_a) : g_rows[base + row_a];
    const bool okA = (tok >= 0);
    const int a_sz = okA ? 16 : 0;
    const __half* ax = xh + (size_t)(okA ? tok : 0) * NH + 8 * qa;
    const int bkk = tid >> 4, bc = tid & 15;
    const uint32_t a_dst = sbase + (row_a * A_W + 4 * qa) * 4;
    const uint32_t bg_dst = sbase + (A_BUFW + bkk * B_W + 4 * bc) * 4;
    const uint32_t bu_dst = bg_dst + B_BUFW * 4;
    const __half* wgp = wg + (size_t)bkk * NM + m0 + 8 * bc;
    const __half* wup = wu + (size_t)bkk * NM + m0 + 8 * bc;

    float dg[2][4][4], du[2][4][4];
#pragma unroll
    for (int a1 = 0; a1 < 2; a1++)
#pragma unroll
        for (int b1 = 0; b1 < 4; b1++)
#pragma unroll
            for (int c1 = 0; c1 < 4; c1++) { dg[a1][b1][c1] = 0.f; du[a1][b1][c1] = 0.f; }

    const int KC = NH / 32;
#pragma unroll
    for (int s = 0; s < 3; s++) {
        uint32_t so = s * SW1 * 4;
        cpa16(a_dst + so, ax + s * 32, a_sz);
        cpa16(bg_dst + so, wgp + (size_t)s * 32 * NM, 16);
        cpa16(bu_dst + so, wup + (size_t)s * 32 * NM, 16);
        CP_COMMIT();
    }

    for (int kc = 0; kc < KC; kc++) {
        CP_WAIT2();
        __syncthreads();
        const int st = kc & 3;
        const uint32_t asb = sbase + (st * SW1) * 4;
        const uint32_t bgb = asb + A_BUFW * 4;
        const uint32_t bub = bgb + B_BUFW * 4;
#pragma unroll
        for (int ks = 0; ks < 2; ks++) {
            uint32_t a[2][4];
#pragma unroll
            for (int mi = 0; mi < 2; mi++)
                ldsm4(a[mi], asb + ((a_row + mi * 16) * A_W + ks * 8 + a_coff) * 4);
            uint32_t fg[2][4], fu[2][4];
#pragma unroll
            for (int nip = 0; nip < 2; nip++) {
                uint32_t boff = ((b_krow + ks * 16) * B_W + b_coff + nip * 8) * 4;
                ldsm4t(fg[nip], bgb + boff);
                ldsm4t(fu[nip], bub + boff);
            }
#pragma unroll
            for (int ni = 0; ni < 4; ni++) {
                int nip = ni >> 1, o = (ni & 1) * 2;
#pragma unroll
                for (int mi = 0; mi < 2; mi++) {
                    mma16(dg[mi][ni], a[mi], fg[nip][o], fg[nip][o + 1]);
                    mma16(du[mi][ni], a[mi], fu[nip][o], fu[nip][o + 1]);
                }
            }
        }
        int nk = kc + 3;
        if (nk < KC) {
            uint32_t so = (nk & 3) * SW1 * 4;
            cpa16(a_dst + so, ax + nk * 32, a_sz);
            cpa16(bg_dst + so, wgp + (size_t)nk * 32 * NM, 16);
            cpa16(bu_dst + so, wup + (size_t)nk * 32 * NM, 16);
        }
        CP_COMMIT();
    }

    const int hb = (SHARED ? SHARED_HBASE : 0) + base;
    uint32_t* h32 = (uint32_t*)g_hbuf;
#pragma unroll
    for (int mi = 0; mi < 2; mi++)
#pragma unroll
        for (int ni = 0; ni < 4; ni++) {
            int r = hb + wm + 16 * mi + g;
            int cw = (m0 + wn + 8 * ni + 2 * j) >> 1;
            h32[(size_t)r * (NM / 2) + cw] =
                pack2(silu_f(dg[mi][ni][0]) * du[mi][ni][0],
                      silu_f(dg[mi][ni][1]) * du[mi][ni][1]);
            h32[(size_t)(r + 8) * (NM / 2) + cw] =
                pack2(silu_f(dg[mi][ni][2]) * du[mi][ni][2],
                      silu_f(dg[mi][ni][3]) * du[mi][ni][3]);
        }
}

// ---------------- GEMM2: out/eout = h @ Wd, CTA 128m x 128n, 512 thr ----------------
template <bool SHARED>
__global__ void __launch_bounds__(512)
moe_gemm2_mma(const __half* __restrict__ Wd, float* __restrict__ out) {
    extern __shared__ uint32_t smw[];
    int by = blockIdx.y, e, base;
    if (SHARED) { e = 0; base = by * 128; }
    else {
        if (by >= g_num_tiles) return;
        e = g_tile_e[by];
        base = g_tile_base[by];
    }
    const int n0 = blockIdx.x * 128;
    const __half* wd = Wd + (size_t)e * NM * NH;
    const int hb = (SHARED ? SHARED_HBASE : 0) + base;

    const uint32_t sbase = smem_u32(smw);
    const int tid = threadIdx.x;
    const int lane = tid & 31, wid = tid >> 5;
    const int j = lane & 3, g = lane >> 2;
    const int wm = (wid & 3) * 32, wn = (wid >> 2) * 32;

    const int a_row  = wm + ((lane >> 3) & 1) * 8 + (lane & 7);
    const int a_coff = (lane >> 4) * 4;
    const int b_krow = ((lane >> 3) & 1) * 8 + (lane & 7);
    const int b_coff = (wn >> 1) + (lane >> 4) * 4;

    const int row_a = tid & 127, qa = tid >> 7;
    const __half* ax = g_hbuf + (size_t)(hb + row_a) * NM + 8 * qa;
    const int bkk = tid >> 4, bc = tid & 15;
    const uint32_t a_dst = sbase + (row_a * A_W + 4 * qa) * 4;
    const uint32_t b_dst = sbase + (A_BUFW + bkk * B_W + 4 * bc) * 4;
    const __half* wdp = wd + (size_t)bkk * NH + n0 + 8 * bc;

    float d[2][4][4];
#pragma unroll
    for (int a1 = 0; a1 < 2; a1++)
#pragma unroll
        for (int b1 = 0; b1 < 4; b1++)
#pragma unroll
            for (int c1 = 0; c1 < 4; c1++) d[a1][b1][c1] = 0.f;

    const int KC = NM / 32;
#pragma unroll
    for (int s = 0; s < 3; s++) {
        uint32_t so = s * SW2 * 4;
        cpa16(a_dst + so, ax + s * 32, 16);
        cpa16(b_dst + so, wdp + (size_t)s * 32 * NH, 16);
        CP_COMMIT();
    }

    for (int kc = 0; kc < KC; kc++) {
        CP_WAIT2();
        __syncthreads();
        const int st = kc & 3;
        const uint32_t asb = sbase + (st * SW2) * 4;
        const uint32_t bsb = asb + A_BUFW * 4;
#pragma unroll
        for (int ks = 0; ks < 2; ks++) {
            uint32_t a[2][4];
#pragma unroll
            for (int mi = 0; mi < 2; mi++)
                ldsm4(a[mi], asb + ((a_row + mi * 16) * A_W + ks * 8 + a_coff) * 4);
            uint32_t fb[2][4];
#pragma unroll
            for (int nip = 0; nip < 2; nip++)
                ldsm4t(fb[nip], bsb + ((b_krow + ks * 16) * B_W + b_coff + nip * 8) * 4);
#pragma unroll
            for (int ni = 0; ni < 4; ni++) {
                int nip = ni >> 1, o = (ni & 1) * 2;
#pragma unroll
                for (int mi = 0; mi < 2; mi++)
                    mma16(d[mi][ni], a[mi], fb[nip][o], fb[nip][o + 1]);
            }
        }
        int nk = kc + 3;
        if (nk < KC) {
            uint32_t so = (nk & 3) * SW2 * 4;
            cpa16(a_dst + so, ax + nk * 32, 16);
            cpa16(b_dst + so, wdp + (size_t)nk * 32 * NH, 16);
        }
        CP_COMMIT();
    }

#pragma unroll
    for (int mi = 0; mi < 2; mi++)
#pragma unroll
        for (int ni = 0; ni < 4; ni++) {
            int r = base + wm + 16 * mi + g;
            int col = n0 + wn + 8 * ni + 2 * j;
            float* dst0 = SHARED ? (out + (size_t)r * NH + col)
                                 : (g_eout + (size_t)r * NH + col);
            float* dst1 = SHARED ? (out + (size_t)(r + 8) * NH + col)
                                 : (g_eout + (size_t)(r + 8) * NH + col);
            *(float2*)dst0 = make_float2(d[mi][ni][0], d[mi][ni][1]);
            *(float2*)dst1 = make_float2(d[mi][ni][2], d[mi][ni][3]);
        }
}

// ---------------- combine ----------------
__global__ void moe_combine(float* __restrict__ out) {
    int t = blockIdx.x;
    int h = threadIdx.x * 4;
    int s0 = g_tok2slot[2 * t + 0], s1 = g_tok2slot[2 * t + 1];
    float p0 = g_topk_prob[2 * t + 0], p1 = g_topk_prob[2 * t + 1];
    float4 o = *(float4*)(out + (size_t)t * NH + h);
    float4 a = *(const float4*)(g_eout + (size_t)s0 * NH + h);
    float4 b = *(const float4*)(g_eout + (size_t)s1 * NH + h);
    o.x += p0 * a.x + p1 * b.x;
    o.y += p0 * a.y + p1 * b.y;
    o.z += p0 * a.z + p1 * b.z;
    o.w += p0 * a.w + p1 * b.w;
    *(float4*)(out + (size_t)t * NH + h) = o;
}

// ---------------- launch ----------------
extern "C" void kernel_launch(void* const* d_in, const int* in_sizes, int n_in,
                              void* d_out, int out_size) {
    const float* x    = (const float*)d_in[0];
    const float* gw   = (const float*)d_in[1];
    const float* beta = (const float*)d_in[2];
    const float* gpw  = (const float*)d_in[3];
    const float* upw  = (const float*)d_in[4];
    const float* dpw  = (const float*)d_in[5];
    const float* sgw  = (const float*)d_in[6];
    const float* suw  = (const float*)d_in[7];
    const float* sdw  = (const float*)d_in[8];
    float* out = (float*)d_out;

    static __half *wgh = nullptr, *wuh = nullptr, *wdh = nullptr,
                  *sgh = nullptr, *suh = nullptr, *sdh = nullptr, *xh = nullptr;
    static cudaStream_t s1 = nullptr;
    static cudaEvent_t ev_fork = nullptr, ev_cvt = nullptr;
    if (!wgh) {
        void* p;
        cudaGetSymbolAddress(&p, g_wgh); wgh = (__half*)p;
        cudaGetSymbolAddress(&p, g_wuh); wuh = (__half*)p;
        cudaGetSymbolAddress(&p, g_wdh); wdh = (__half*)p;
        cudaGetSymbolAddress(&p, g_sgh); sgh = (__half*)p;
        cudaGetSymbolAddress(&p, g_suh); suh = (__half*)p;
        cudaGetSymbolAddress(&p, g_sdh); sdh = (__half*)p;
        cudaGetSymbolAddress(&p, g_xh);  xh  = (__half*)p;
        cudaFuncSetAttribute(moe_gemm1_mma<false>, cudaFuncAttributeMaxDynamicSharedMemorySize, SMEM1_BYTES);
        cudaFuncSetAttribute(moe_gemm1_mma<true>,  cudaFuncAttributeMaxDynamicSharedMemorySize, SMEM1_BYTES);
        cudaFuncSetAttribute(moe_gemm2_mma<false>, cudaFuncAttributeMaxDynamicSharedMemorySize, SMEM2_BYTES);
        cudaFuncSetAttribute(moe_gemm2_mma<true>,  cudaFuncAttributeMaxDynamicSharedMemorySize, SMEM2_BYTES);
        cudaStreamCreateWithFlags(&s1, cudaStreamNonBlocking);
        cudaEventCreateWithFlags(&ev_fork, cudaEventDisableTiming);
        cudaEventCreateWithFlags(&ev_cvt, cudaEventDisableTiming);
    }

    const int NBIG = NE * NH * NM / 8;      // per big weight tensor
    const int NSML = NH * NM / 8;

    // Fork: big expert-weight conversions on side stream s1.
    cudaEventRecord(ev_fork, 0);
    cudaStreamWaitEvent(s1, ev_fork, 0);
    cvt8<<<(NBIG + 255) / 256, 256, 0, s1>>>((const float4*)gpw, (uint4*)wgh, NBIG);
    cvt8<<<(NBIG + 255) / 256, 256, 0, s1>>>((const float4*)upw, (uint4*)wuh, NBIG);
    cvt8<<<(NBIG + 255) / 256, 256, 0, s1>>>((const float4*)dpw, (uint4*)wdh, NBIG);
    cudaEventRecord(ev_cvt, s1);

    // Main stream: small cvts + routing + shared-expert chain (independent of big cvts).
    cvt8<<<(NSML + 255) / 256, 256>>>((const float4*)sgw, (uint4*)sgh, NSML);
    cvt8<<<(NSML + 255) / 256, 256>>>((const float4*)suw, (uint4*)suh, NSML);
    cvt8<<<(NSML + 255) / 256, 256>>>((const float4*)sdw, (uint4*)sdh, NSML);
    moe_route<<<NTOK, 256>>>(x, gw, beta);
    moe_build<<<1, 512>>>();

    moe_gemm1_mma<true><<<dim3(NM / 128, NTOK / 128), 512, SMEM1_BYTES>>>(xh, sgh, suh);
    moe_gemm2_mma<true><<<dim3(NH / 128, NTOK / 128), 512, SMEM2_BYTES>>>(sdh, out);

    // Join: routed chain needs converted expert weights.
    cudaStreamWaitEvent(0, ev_cvt, 0);
    moe_gemm1_mma<false><<<dim3(NM / 128, 40), 512, SMEM1_BYTES>>>(xh, wgh, wuh);
    moe_gemm2_mma<false><<<dim3(NH / 128, 40), 512, SMEM2_BYTES>>>(wdh, out);

    moe_combine<<<NTOK, 256>>>(out);
}

// round 15
// speedup vs baseline: 2.5630x; 1.0568x over previous
#include <cuda_runtime.h>
#include <cuda_fp16.h>
#include <cstdint>

#define NE   8
#define NH   1024
#define NM   2048
#define NTOK 2048
#define SLOT_CAP     6144
#define SHARED_HBASE 6144
#define HROWS        8192
#define MAX_TILES    48

// fp16 smem layouts (word = 4B = 2 fp16)
#define A_W    20
#define A_BUFW 2560    // 128 * 20
#define B_W    68
#define B_BUFW 2176    // 32 * 68
#define SW1    (A_BUFW + 2 * B_BUFW)   // gemm1 stage words
#define SW2    (A_BUFW + B_BUFW)       // gemm2 stage words
#define SMEM1_BYTES (4 * SW1 * 4)      // 110592
#define SMEM2_BYTES (4 * SW2 * 4)      // 75776

// ---------------- device scratch ----------------
__device__ int    g_rows[SLOT_CAP];
__device__ float  g_wts[SLOT_CAP];
__device__ int    g_tile_e[MAX_TILES];
__device__ int    g_tile_base[MAX_TILES];
__device__ int    g_num_tiles;
__device__ int    g_topk_idx[NTOK * 2];
__device__ float  g_topk_prob[NTOK * 2];
__device__ __half g_hbuf[(size_t)HROWS * NM];
__device__ __half g_xh[(size_t)NTOK * NH];
__device__ __half g_wgh[(size_t)NE * NH * NM];
__device__ __half g_wuh[(size_t)NE * NH * NM];
__device__ __half g_wdh[(size_t)NE * NM * NH];
__device__ __half g_sgh[(size_t)NH * NM];
__device__ __half g_suh[(size_t)NH * NM];
__device__ __half g_sdh[(size_t)NM * NH];

// ---------------- helpers ----------------
__device__ __forceinline__ uint32_t smem_u32(const void* p) {
    uint32_t a;
    asm("{ .reg .u64 t; cvta.to.shared.u64 t, %1; cvt.u32.u64 %0, t; }" : "=r"(a) : "l"(p));
    return a;
}
__device__ __forceinline__ uint32_t pack2(float lo, float hi) {
    __half2 h = __floats2half2_rn(lo, hi);
    return *(uint32_t*)&h;
}
__device__ __forceinline__ float silu_f(float v) { return v / (1.0f + __expf(-v)); }

__device__ __forceinline__ void cpa16(uint32_t dst, const void* src, int szbytes) {
    asm volatile("cp.async.cg.shared.global [%0], [%1], 16, %2;"
        :: "r"(dst), "l"(src), "r"(szbytes) : "memory");
}
#define CP_COMMIT() asm volatile("cp.async.commit_group;" ::: "memory")
#define CP_WAIT2()  asm volatile("cp.async.wait_group 2;" ::: "memory")

__device__ __forceinline__ void ldsm4(uint32_t* r, uint32_t addr) {
    asm volatile("ldmatrix.sync.aligned.m8n8.x4.shared.b16 {%0,%1,%2,%3}, [%4];"
        : "=r"(r[0]), "=r"(r[1]), "=r"(r[2]), "=r"(r[3]) : "r"(addr));
}
__device__ __forceinline__ void ldsm4t(uint32_t* r, uint32_t addr) {
    asm volatile("ldmatrix.sync.aligned.m8n8.x4.trans.shared.b16 {%0,%1,%2,%3}, [%4];"
        : "=r"(r[0]), "=r"(r[1]), "=r"(r[2]), "=r"(r[3]) : "r"(addr));
}
__device__ __forceinline__ void mma16(float* d, const uint32_t* a, uint32_t b0, uint32_t b1) {
    asm volatile(
        "mma.sync.aligned.m16n8k16.row.col.f32.f16.f16.f32 "
        "{%0,%1,%2,%3},{%4,%5,%6,%7},{%8,%9},{%0,%1,%2,%3};"
        : "+f"(d[0]), "+f"(d[1]), "+f"(d[2]), "+f"(d[3])
        : "r"(a[0]), "r"(a[1]), "r"(a[2]), "r"(a[3]), "r"(b0), "r"(b1));
}

// ---------------- fused fp32->fp16 convert of 3 tensors ----------------
__global__ void cvt8x3(const float4* __restrict__ s0, const float4* __restrict__ s1,
                       const float4* __restrict__ s2,
                       uint4* __restrict__ d0, uint4* __restrict__ d1,
                       uint4* __restrict__ d2, int n8) {
    int i = blockIdx.x * blockDim.x + threadIdx.x;
    const float4* s;
    uint4* d;
    int k;
    if (i < n8)          { s = s0; d = d0; k = i; }
    else if (i < 2 * n8) { s = s1; d = d1; k = i - n8; }
    else if (i < 3 * n8) { s = s2; d = d2; k = i - 2 * n8; }
    else return;
    float4 a = s[2 * k], b = s[2 * k + 1];
    d[k] = make_uint4(pack2(a.x, a.y), pack2(a.z, a.w),
                      pack2(b.x, b.y), pack2(b.z, b.w));
}

// ---------------- routing (also emits fp16 x) ----------------
__global__ void moe_route(const float* __restrict__ x,
                          const float* __restrict__ gw,
                          const float* __restrict__ beta) {
    int b = blockIdx.x;
    const float* xr = x + (size_t)b * NH;
    float acc[NE];
#pragma unroll
    for (int e = 0; e < NE; e++) acc[e] = 0.f;
    for (int h = threadIdx.x; h < NH; h += 256) {
        float xv = xr[h];
        g_xh[(size_t)b * NH + h] = __float2half(xv);
#pragma unroll
        for (int e = 0; e < NE; e++) acc[e] += xv * gw[e * NH + h];
    }
#pragma unroll
    for (int off = 16; off > 0; off >>= 1)
#pragma unroll
        for (int e = 0; e < NE; e++)
            acc[e] += __shfl_down_sync(0xFFFFFFFFu, acc[e], off);
    __shared__ float part[8][NE];
    int lane = threadIdx.x & 31, warp = threadIdx.x >> 5;
    if (lane == 0)
#pragma unroll
        for (int e = 0; e < NE; e++) part[warp][e] = acc[e];
    __syncthreads();
    if (threadIdx.x == 0) {
        float lg[NE];
#pragma unroll
        for (int e = 0; e < NE; e++) {
            float s = 0.f;
#pragma unroll
            for (int w = 0; w < 8; w++) s += part[w][e];
            lg[e] = s;
        }
        int i1 = 0; float b1 = -1e30f;
#pragma unroll
        for (int e = 0; e < NE; e++) {
            float v = lg[e] + beta[e];
            if (v > b1) { b1 = v; i1 = e; }
        }
        int i2 = -1; float b2 = -1e30f;
#pragma unroll
        for (int e = 0; e < NE; e++) {
            if (e == i1) continue;
            float v = lg[e] + beta[e];
            if (v > b2) { b2 = v; i2 = e; }
        }
        g_topk_idx[2 * b + 0] = i1;
        g_topk_prob[2 * b + 0] = 1.f / (1.f + __expf(-lg[i1]));
        g_topk_idx[2 * b + 1] = i2;
        g_topk_prob[2 * b + 1] = 1.f / (1.f + __expf(-lg[i2]));
    }
}

__global__ void moe_build() {
    __shared__ int cnt[NE], fill[NE], seg[NE];
    int tid = threadIdx.x;
    for (int i = tid; i < SLOT_CAP; i += blockDim.x) g_rows[i] = -1;
    if (tid < NE) { cnt[tid] = 0; fill[tid] = 0; }
    __syncthreads();
    for (int i = tid; i < NTOK * 2; i += blockDim.x)
        atomicAdd(&cnt[g_topk_idx[i]], 1);
    __syncthreads();
    if (tid == 0) {
        int off = 0, nt = 0;
        for (int e = 0; e < NE; e++) {
            seg[e] = off;
            int tiles = (cnt[e] + 127) >> 7;
            for (int t = 0; t < tiles; t++) {
                g_tile_e[nt] = e;
                g_tile_base[nt] = off + (t << 7);
                nt++;
            }
            off += tiles << 7;
        }
        g_num_tiles = nt;
    }
    __syncthreads();
    for (int i = tid; i < NTOK * 2; i += blockDim.x) {
        int e = g_topk_idx[i];
        int p = seg[e] + atomicAdd(&fill[e], 1);
        g_rows[p] = i >> 1;
        g_wts[p]  = g_topk_prob[i];
    }
}

// ---------------- GEMM1: h = silu(x@Wg)*(x@Wu), CTA 128m x 128n, 512 thr ----------------
template <bool SHARED>
__global__ void __launch_bounds__(512)
moe_gemm1_mma(const __half* __restrict__ xh,
              const __half* __restrict__ Wg,
              const __half* __restrict__ Wu) {
    extern __shared__ uint32_t smw[];
    int by = blockIdx.y, e, base;
    if (SHARED) { e = 0; base = by * 128; }
    else {
        if (by >= g_num_tiles) return;
        e = g_tile_e[by];
        base = g_tile_base[by];
    }
    const int m0 = blockIdx.x * 128;
    const __half* wg = Wg + (size_t)e * NH * NM;
    const __half* wu = Wu + (size_t)e * NH * NM;

    const uint32_t sbase = smem_u32(smw);
    const int tid = threadIdx.x;
    const int lane = tid & 31, wid = tid >> 5;
    const int j = lane & 3, g = lane >> 2;
    const int wm = (wid & 3) * 32, wn = (wid >> 2) * 32;

    const int a_row  = wm + ((lane >> 3) & 1) * 8 + (lane & 7);
    const int a_coff = (lane >> 4) * 4;
    const int b_krow = ((lane >> 3) & 1) * 8 + (lane & 7);
    const int b_coff = (wn >> 1) + (lane >> 4) * 4;

    const int row_a = tid & 127, qa = tid >> 7;
    int tok = SHARED ? (base + row_a) : g_rows[base + row_a];
    const bool okA = (tok >= 0);
    const int a_sz = okA ? 16 : 0;
    const __half* ax = xh + (size_t)(okA ? tok : 0) * NH + 8 * qa;
    const int bkk = tid >> 4, bc = tid & 15;
    const uint32_t a_dst = sbase + (row_a * A_W + 4 * qa) * 4;
    const uint32_t bg_dst = sbase + (A_BUFW + bkk * B_W + 4 * bc) * 4;
    const uint32_t bu_dst = bg_dst + B_BUFW * 4;
    const __half* wgp = wg + (size_t)bkk * NM + m0 + 8 * bc;
    const __half* wup = wu + (size_t)bkk * NM + m0 + 8 * bc;

    float dg[2][4][4], du[2][4][4];
#pragma unroll
    for (int a1 = 0; a1 < 2; a1++)
#pragma unroll
        for (int b1 = 0; b1 < 4; b1++)
#pragma unroll
            for (int c1 = 0; c1 < 4; c1++) { dg[a1][b1][c1] = 0.f; du[a1][b1][c1] = 0.f; }

    const int KC = NH / 32;
#pragma unroll
    for (int s = 0; s < 3; s++) {
        uint32_t so = s * SW1 * 4;
        cpa16(a_dst + so, ax + s * 32, a_sz);
        cpa16(bg_dst + so, wgp + (size_t)s * 32 * NM, 16);
        cpa16(bu_dst + so, wup + (size_t)s * 32 * NM, 16);
        CP_COMMIT();
    }

    for (int kc = 0; kc < KC; kc++) {
        CP_WAIT2();
        __syncthreads();
        const int st = kc & 3;
        const uint32_t asb = sbase + (st * SW1) * 4;
        const uint32_t bgb = asb + A_BUFW * 4;
        const uint32_t bub = bgb + B_BUFW * 4;
#pragma unroll
        for (int ks = 0; ks < 2; ks++) {
            uint32_t a[2][4];
#pragma unroll
            for (int mi = 0; mi < 2; mi++)
                ldsm4(a[mi], asb + ((a_row + mi * 16) * A_W + ks * 8 + a_coff) * 4);
            uint32_t fg[2][4], fu[2][4];
#pragma unroll
            for (int nip = 0; nip < 2; nip++) {
                uint32_t boff = ((b_krow + ks * 16) * B_W + b_coff + nip * 8) * 4;
                ldsm4t(fg[nip], bgb + boff);
                ldsm4t(fu[nip], bub + boff);
            }
#pragma unroll
            for (int ni = 0; ni < 4; ni++) {
                int nip = ni >> 1, o = (ni & 1) * 2;
#pragma unroll
                for (int mi = 0; mi < 2; mi++) {
                    mma16(dg[mi][ni], a[mi], fg[nip][o], fg[nip][o + 1]);
                    mma16(du[mi][ni], a[mi], fu[nip][o], fu[nip][o + 1]);
                }
            }
        }
        int nk = kc + 3;
        if (nk < KC) {
            uint32_t so = (nk & 3) * SW1 * 4;
            cpa16(a_dst + so, ax + nk * 32, a_sz);
            cpa16(bg_dst + so, wgp + (size_t)nk * 32 * NM, 16);
            cpa16(bu_dst + so, wup + (size_t)nk * 32 * NM, 16);
        }
        CP_COMMIT();
    }

    const int hb = (SHARED ? SHARED_HBASE : 0) + base;
    uint32_t* h32 = (uint32_t*)g_hbuf;
#pragma unroll
    for (int mi = 0; mi < 2; mi++)
#pragma unroll
        for (int ni = 0; ni < 4; ni++) {
            int r = hb + wm + 16 * mi + g;
            int cw = (m0 + wn + 8 * ni + 2 * j) >> 1;
            h32[(size_t)r * (NM / 2) + cw] =
                pack2(silu_f(dg[mi][ni][0]) * du[mi][ni][0],
                      silu_f(dg[mi][ni][1]) * du[mi][ni][1]);
            h32[(size_t)(r + 8) * (NM / 2) + cw] =
                pack2(silu_f(dg[mi][ni][2]) * du[mi][ni][2],
                      silu_f(dg[mi][ni][3]) * du[mi][ni][3]);
        }
}

// ---------------- GEMM2: out += h @ Wd, CTA 128m x 128n, 256 thr, warp 32m x 64n ----------
template <bool SHARED>
__global__ void __launch_bounds__(256, 2)
moe_gemm2_mma(const __half* __restrict__ Wd, float* __restrict__ out) {
    extern __shared__ uint32_t smw[];
    int by = blockIdx.y, e, base;
    if (SHARED) { e = 0; base = by * 128; }
    else {
        if (by >= g_num_tiles) return;
        e = g_tile_e[by];
        base = g_tile_base[by];
    }
    const int n0 = blockIdx.x * 128;
    const __half* wd = Wd + (size_t)e * NM * NH;
    const int hb = (SHARED ? SHARED_HBASE : 0) + base;

    const uint32_t sbase = smem_u32(smw);
    const int tid = threadIdx.x;
    const int lane = tid & 31, wid = tid >> 5;     // 8 warps
    const int j = lane & 3, g = lane >> 2;
    const int wm = (wid & 3) * 32, wn = (wid >> 2) * 64;

    const int a_row  = wm + ((lane >> 3) & 1) * 8 + (lane & 7);
    const int a_coff = (lane >> 4) * 4;
    const int b_krow = ((lane >> 3) & 1) * 8 + (lane & 7);
    const int b_coff = (wn >> 1) + (lane >> 4) * 4;

    // loaders: 256 threads; A: 128 rows x 4 chunks -> 2 per thread; B same
    const int row_a = tid & 127, qa0 = (tid >> 7) * 2;
    const __half* ax = g_hbuf + (size_t)(hb + row_a) * NM + 8 * qa0;
    const int bkk = tid >> 3, bc0 = (tid & 7) * 2;
    const uint32_t a_dst = sbase + (row_a * A_W + 4 * qa0) * 4;
    const uint32_t b_dst = sbase + (A_BUFW + bkk * B_W + 4 * bc0) * 4;
    const __half* wdp = wd + (size_t)bkk * NH + n0 + 8 * bc0;

    float d[2][8][4];
#pragma unroll
    for (int a1 = 0; a1 < 2; a1++)
#pragma unroll
        for (int b1 = 0; b1 < 8; b1++)
#pragma unroll
            for (int c1 = 0; c1 < 4; c1++) d[a1][b1][c1] = 0.f;

    const int KC = NM / 32;
#pragma unroll
    for (int s = 0; s < 3; s++) {
        uint32_t so = s * SW2 * 4;
        cpa16(a_dst + so, ax + s * 32, 16);
        cpa16(a_dst + so + 16, ax + s * 32 + 8, 16);
        cpa16(b_dst + so, wdp + (size_t)s * 32 * NH, 16);
        cpa16(b_dst + so + 16, wdp + (size_t)s * 32 * NH + 8, 16);
        CP_COMMIT();
    }

    for (int kc = 0; kc < KC; kc++) {
        CP_WAIT2();
        __syncthreads();
        const int st = kc & 3;
        const uint32_t asb = sbase + (st * SW2) * 4;
        const uint32_t bsb = asb + A_BUFW * 4;
#pragma unroll
        for (int ks = 0; ks < 2; ks++) {
            uint32_t a[2][4];
#pragma unroll
            for (int mi = 0; mi < 2; mi++)
                ldsm4(a[mi], asb + ((a_row + mi * 16) * A_W + ks * 8 + a_coff) * 4);
            uint32_t fb[4][4];
#pragma unroll
            for (int nip = 0; nip < 4; nip++)
                ldsm4t(fb[nip], bsb + ((b_krow + ks * 16) * B_W + b_coff + nip * 8) * 4);
#pragma unroll
            for (int ni = 0; ni < 8; ni++) {
                int nip = ni >> 1, o = (ni & 1) * 2;
#pragma unroll
                for (int mi = 0; mi < 2; mi++)
                    mma16(d[mi][ni], a[mi], fb[nip][o], fb[nip][o + 1]);
            }
        }
        int nk = kc + 3;
        if (nk < KC) {
            uint32_t so = (nk & 3) * SW2 * 4;
            cpa16(a_dst + so, ax + nk * 32, 16);
            cpa16(a_dst + so + 16, ax + nk * 32 + 8, 16);
            cpa16(b_dst + so, wdp + (size_t)nk * 32 * NH, 16);
            cpa16(b_dst + so + 16, wdp + (size_t)nk * 32 * NH + 8, 16);
        }
        CP_COMMIT();
    }

    if (SHARED) {
#pragma unroll
        for (int mi = 0; mi < 2; mi++)
#pragma unroll
            for (int ni = 0; ni < 8; ni++) {
                int r = base + wm + 16 * mi + g;
                int col = n0 + wn + 8 * ni + 2 * j;
                *(float2*)(out + (size_t)r * NH + col) =
                    make_float2(d[mi][ni][0], d[mi][ni][1]);
                *(float2*)(out + (size_t)(r + 8) * NH + col) =
                    make_float2(d[mi][ni][2], d[mi][ni][3]);
            }
    } else {
#pragma unroll
        for (int mi = 0; mi < 2; mi++) {
            int s0 = base + wm + 16 * mi + g;
            int t0 = g_rows[s0], t1 = g_rows[s0 + 8];
            float w0 = g_wts[s0], w1 = g_wts[s0 + 8];
#pragma unroll
            for (int ni = 0; ni < 8; ni++) {
                int col = n0 + wn + 8 * ni + 2 * j;
                if (t0 >= 0) {
                    atomicAdd(out + (size_t)t0 * NH + col,     w0 * d[mi][ni][0]);
                    atomicAdd(out + (size_t)t0 * NH + col + 1, w0 * d[mi][ni][1]);
                }
                if (t1 >= 0) {
                    atomicAdd(out + (size_t)t1 * NH + col,     w1 * d[mi][ni][2]);
                    atomicAdd(out + (size_t)t1 * NH + col + 1, w1 * d[mi][ni][3]);
                }
            }
        }
    }
}

// ---------------- launch ----------------
extern "C" void kernel_launch(void* const* d_in, const int* in_sizes, int n_in,
                              void* d_out, int out_size) {
    const float* x    = (const float*)d_in[0];
    const float* gw   = (const float*)d_in[1];
    const float* beta = (const float*)d_in[2];
    const float* gpw  = (const float*)d_in[3];
    const float* upw  = (const float*)d_in[4];
    const float* dpw  = (const float*)d_in[5];
    const float* sgw  = (const float*)d_in[6];
    const float* suw  = (const float*)d_in[7];
    const float* sdw  = (const float*)d_in[8];
    float* out = (float*)d_out;

    static __half *wgh = nullptr, *wuh = nullptr, *wdh = nullptr,
                  *sgh = nullptr, *suh = nullptr, *sdh = nullptr, *xh = nullptr;
    static cudaStream_t s1 = nullptr;
    static cudaEvent_t ev_fork = nullptr, ev_cvt = nullptr;
    if (!wgh) {
        void* p;
        cudaGetSymbolAddress(&p, g_wgh); wgh = (__half*)p;
        cudaGetSymbolAddress(&p, g_wuh); wuh = (__half*)p;
        cudaGetSymbolAddress(&p, g_wdh); wdh = (__half*)p;
        cudaGetSymbolAddress(&p, g_sgh); sgh = (__half*)p;
        cudaGetSymbolAddress(&p, g_suh); suh = (__half*)p;
        cudaGetSymbolAddress(&p, g_sdh); sdh = (__half*)p;
        cudaGetSymbolAddress(&p, g_xh);  xh  = (__half*)p;
        cudaFuncSetAttribute(moe_gemm1_mma<false>, cudaFuncAttributeMaxDynamicSharedMemorySize, SMEM1_BYTES);
        cudaFuncSetAttribute(moe_gemm1_mma<true>,  cudaFuncAttributeMaxDynamicSharedMemorySize, SMEM1_BYTES);
        cudaFuncSetAttribute(moe_gemm2_mma<false>, cudaFuncAttributeMaxDynamicSharedMemorySize, SMEM2_BYTES);
        cudaFuncSetAttribute(moe_gemm2_mma<true>,  cudaFuncAttributeMaxDynamicSharedMemorySize, SMEM2_BYTES);
        cudaStreamCreateWithFlags(&s1, cudaStreamNonBlocking);
        cudaEventCreateWithFlags(&ev_fork, cudaEventDisableTiming);
        cudaEventCreateWithFlags(&ev_cvt, cudaEventDisableTiming);
    }

    const int NBIG = NE * NH * NM / 8;
    const int NSML = NH * NM / 8;

    // Fork: one fused conversion kernel for the 3 big expert-weight tensors.
    cudaEventRecord(ev_fork, 0);
    cudaStreamWaitEvent(s1, ev_fork, 0);
    cvt8x3<<<(3 * NBIG + 255) / 256, 256, 0, s1>>>(
        (const float4*)gpw, (const float4*)upw, (const float4*)dpw,
        (uint4*)wgh, (uint4*)wuh, (uint4*)wdh, NBIG);
    cudaEventRecord(ev_cvt, s1);

    // Main stream: shared-expert chain.
    cvt8x3<<<(3 * NSML + 255) / 256, 256>>>(
        (const float4*)sgw, (const float4*)suw, (const float4*)sdw,
        (uint4*)sgh, (uint4*)suh, (uint4*)sdh, NSML);
    moe_route<<<NTOK, 256>>>(x, gw, beta);
    moe_build<<<1, 512>>>();

    moe_gemm1_mma<true><<<dim3(NM / 128, NTOK / 128), 512, SMEM1_BYTES>>>(xh, sgh, suh);
    moe_gemm2_mma<true><<<dim3(NH / 128, NTOK / 128), 256, SMEM2_BYTES>>>(sdh, out);

    // Join, then routed chain (gemm2 accumulates into out with atomics).
    cudaStreamWaitEvent(0, ev_cvt, 0);
    moe_gemm1_mma<false><<<dim3(NM / 128, 40), 512, SMEM1_BYTES>>>(xh, wgh, wuh);
    moe_gemm2_mma<false><<<dim3(NH / 128, 40), 256, SMEM2_BYTES>>>(wdh, out);
}